// round 3
// baseline (speedup 1.0000x reference)
#include <cuda_runtime.h>
#include <math.h>

// Problem constants (fixed by the dataset): B=4, S=2048, H=D=2048, fp32.
#define BATCH 4
#define SEQ   2048
#define HID   2048
#define MROWS (BATCH * SEQ)          // 8192 GEMM rows

// Segmented scan config
#define NSEG  16
#define SEG   (SEQ / NSEG)           // 128
#define NCH   (BATCH * HID)          // 8192 channels

// ---------------------------------------------------------------------------
// Scratch (device globals: allocation is forbidden)
// ---------------------------------------------------------------------------
__device__ float g_K[(size_t)MROWS * HID];   // k = mix_k(hidden) @ Wk^T
__device__ float g_V[(size_t)MROWS * HID];   // v
__device__ float g_R[(size_t)MROWS * HID];   // sigmoid(r); later overwritten with r*wkv

__device__ float g_sn[NCH * NSEG], g_sd[NCH * NSEG], g_sm[NCH * NSEG]; // segment summaries
__device__ float g_pn[NCH * NSEG], g_pd[NCH * NSEG], g_pm[NCH * NSEG]; // exclusive prefixes

// ---------------------------------------------------------------------------
// GEMM: C[m,n] = sum_k A'[m,k] * W[n,k]
//   A' = A (plain) or time-mixed A (hidden*mix + shifted*(1-mix)) when MIX.
//   128x128 block tile, BK=16, 8x8 per thread, register prefetch pipeline.
// ---------------------------------------------------------------------------
template<bool MIX>
__device__ __forceinline__ float4 loadA4(const float* __restrict__ A,
                                         const float* __restrict__ mix,
                                         int m, int koff)
{
    const float* p = A + (size_t)m * HID + koff;
    float4 h = *reinterpret_cast<const float4*>(p);
    if (MIX) {
        float4 pv;
        if ((m & (SEQ - 1)) == 0) {               // s == 0 -> shifted row is zero
            pv = make_float4(0.f, 0.f, 0.f, 0.f);
        } else {
            pv = *reinterpret_cast<const float4*>(p - HID);
        }
        float4 t = *reinterpret_cast<const float4*>(mix + koff);
        h.x = fmaf(t.x, h.x - pv.x, pv.x);
        h.y = fmaf(t.y, h.y - pv.y, pv.y);
        h.z = fmaf(t.z, h.z - pv.z, pv.z);
        h.w = fmaf(t.w, h.w - pv.w, pv.w);
    }
    return h;
}

template<bool MIX>
__device__ __forceinline__ void gemm_core(const float* __restrict__ A,
                                          const float* __restrict__ W,
                                          const float* __restrict__ mix,
                                          float* __restrict__ C,
                                          bool sig)
{
    constexpr int BM = 128, BN = 128, BK = 16;
    __shared__ float As[BK][BM + 4];   // +4 pad: stride 132 floats (16B-aligned rows)
    __shared__ float Bs[BK][BN + 4];

    const int tid = threadIdx.x;
    const int m0 = blockIdx.y * BM;
    const int n0 = blockIdx.x * BN;
    const int lr = tid >> 2;           // 0..63  (tile row for loads)
    const int lc = (tid & 3) << 2;     // 0,4,8,12 (k-column group)
    const int ty = tid >> 4;           // 0..15
    const int tx = tid & 15;           // 0..15

    float acc[8][8];
#pragma unroll
    for (int i = 0; i < 8; i++)
#pragma unroll
        for (int j = 0; j < 8; j++) acc[i][j] = 0.f;

    // prefetch tile 0 into registers
    float4 a0 = loadA4<MIX>(A, mix, m0 + lr,      lc);
    float4 a1 = loadA4<MIX>(A, mix, m0 + lr + 64, lc);
    float4 b0 = *reinterpret_cast<const float4*>(W + (size_t)(n0 + lr)      * HID + lc);
    float4 b1 = *reinterpret_cast<const float4*>(W + (size_t)(n0 + lr + 64) * HID + lc);

    for (int kt = 0; kt < HID; kt += BK) {
        // stage current prefetch into shared (k-major, transposed)
        As[lc + 0][lr]      = a0.x; As[lc + 1][lr]      = a0.y;
        As[lc + 2][lr]      = a0.z; As[lc + 3][lr]      = a0.w;
        As[lc + 0][lr + 64] = a1.x; As[lc + 1][lr + 64] = a1.y;
        As[lc + 2][lr + 64] = a1.z; As[lc + 3][lr + 64] = a1.w;
        Bs[lc + 0][lr]      = b0.x; Bs[lc + 1][lr]      = b0.y;
        Bs[lc + 2][lr]      = b0.z; Bs[lc + 3][lr]      = b0.w;
        Bs[lc + 0][lr + 64] = b1.x; Bs[lc + 1][lr + 64] = b1.y;
        Bs[lc + 2][lr + 64] = b1.z; Bs[lc + 3][lr + 64] = b1.w;
        __syncthreads();

        const int ktn = kt + BK;
        if (ktn < HID) {               // prefetch next tile (hides GMEM latency)
            a0 = loadA4<MIX>(A, mix, m0 + lr,      ktn + lc);
            a1 = loadA4<MIX>(A, mix, m0 + lr + 64, ktn + lc);
            b0 = *reinterpret_cast<const float4*>(W + (size_t)(n0 + lr)      * HID + ktn + lc);
            b1 = *reinterpret_cast<const float4*>(W + (size_t)(n0 + lr + 64) * HID + ktn + lc);
        }

#pragma unroll
        for (int kk = 0; kk < BK; kk++) {
            float4 af0 = *reinterpret_cast<const float4*>(&As[kk][ty * 8]);
            float4 af1 = *reinterpret_cast<const float4*>(&As[kk][ty * 8 + 4]);
            float4 bf0 = *reinterpret_cast<const float4*>(&Bs[kk][tx * 8]);
            float4 bf1 = *reinterpret_cast<const float4*>(&Bs[kk][tx * 8 + 4]);
            float av[8] = {af0.x, af0.y, af0.z, af0.w, af1.x, af1.y, af1.z, af1.w};
            float bv[8] = {bf0.x, bf0.y, bf0.z, bf0.w, bf1.x, bf1.y, bf1.z, bf1.w};
#pragma unroll
            for (int i = 0; i < 8; i++)
#pragma unroll
                for (int j = 0; j < 8; j++)
                    acc[i][j] = fmaf(av[i], bv[j], acc[i][j]);
        }
        __syncthreads();
    }

    // epilogue
#pragma unroll
    for (int i = 0; i < 8; i++) {
        float* cp = C + (size_t)(m0 + ty * 8 + i) * HID + n0 + tx * 8;
        float4 v0 = make_float4(acc[i][0], acc[i][1], acc[i][2], acc[i][3]);
        float4 v1 = make_float4(acc[i][4], acc[i][5], acc[i][6], acc[i][7]);
        if (sig) {
            v0.x = 1.f / (1.f + __expf(-v0.x)); v0.y = 1.f / (1.f + __expf(-v0.y));
            v0.z = 1.f / (1.f + __expf(-v0.z)); v0.w = 1.f / (1.f + __expf(-v0.w));
            v1.x = 1.f / (1.f + __expf(-v1.x)); v1.y = 1.f / (1.f + __expf(-v1.y));
            v1.z = 1.f / (1.f + __expf(-v1.z)); v1.w = 1.f / (1.f + __expf(-v1.w));
        }
        *reinterpret_cast<float4*>(cp)     = v0;
        *reinterpret_cast<float4*>(cp + 4) = v1;
    }
}

// gridDim = (16, 64, 3); z selects k / v / r
__global__ __launch_bounds__(256)
void gemm_kvr(const float* __restrict__ hidden,
              const float* __restrict__ Wk, const float* __restrict__ Wv,
              const float* __restrict__ Wr,
              const float* __restrict__ mk, const float* __restrict__ mv,
              const float* __restrict__ mr)
{
    const int z = blockIdx.z;
    const float* W   = (z == 0) ? Wk : (z == 1) ? Wv : Wr;
    const float* mix = (z == 0) ? mk : (z == 1) ? mv : mr;
    float*       C   = (z == 0) ? g_K : (z == 1) ? g_V : g_R;
    gemm_core<true>(hidden, W, mix, C, z == 2);
}

// out[b,s,h] = sum_d (r*wkv)[b,s,d] * Wo[h,d]
__global__ __launch_bounds__(256)
void gemm_o(const float* __restrict__ Wo, float* __restrict__ out)
{
    gemm_core<false>(g_R, Wo, nullptr, out, false);
}

// ---------------------------------------------------------------------------
// WKV segmented scan.
// State (num, den, mx) is an exp-stabilized linear recurrence -> associative.
//   pass1: per-(b,seg,d) thread runs SEG steps from the identity state,
//          emitting a segment summary.
//   mid:   per-(b,d) thread sequentially combines the NSEG summaries,
//          writing the EXCLUSIVE prefix state per segment.
//   pass3: per-(b,seg,d) thread rescans its segment from the prefix state,
//          emitting outputs and fusing r * wkv in-place into g_R.
// ---------------------------------------------------------------------------
__global__ void scan_pass1(const float* __restrict__ td)
{
    const int tid = blockIdx.x * blockDim.x + threadIdx.x;  // < NCH*NSEG
    const int d   = tid & (HID - 1);
    const int bs  = tid >> 11;          // HID = 2^11
    const int seg = bs & (NSEG - 1);
    const int b   = bs >> 4;            // NSEG = 16

    const float w = -__expf(td[d]);
    const size_t base = (size_t)(b * SEQ + seg * SEG) * HID + d;

    float num = 0.f, den = 0.f, mx = -1e38f;
    for (int i = 0; i < SEG; i++) {
        const size_t off = base + (size_t)i * HID;
        const float k = g_K[off];
        const float v = g_V[off];
        const float mn = fmaxf(mx + w, k);
        const float e1 = __expf(mx + w - mn);
        const float e2 = __expf(k - mn);
        num = e1 * num + e2 * v;
        den = e1 * den + e2;
        mx  = mn;
    }
    g_sn[tid] = num; g_sd[tid] = den; g_sm[tid] = mx;
}

__global__ void scan_mid(const float* __restrict__ td)
{
    const int tid = blockIdx.x * blockDim.x + threadIdx.x;  // < NCH
    const int d = tid & (HID - 1);
    const int b = tid >> 11;

    const float w = -__expf(td[d]);
    const float shift = w * (float)SEG;

    float N = 0.f, Dn = 0.f, M = -1e38f;
    for (int seg = 0; seg < NSEG; seg++) {
        const int idx = ((b * NSEG + seg) << 11) + d;
        g_pn[idx] = N; g_pd[idx] = Dn; g_pm[idx] = M;
        const float sn = g_sn[idx], sd = g_sd[idx], sm = g_sm[idx];
        const float mf = fmaxf(M + shift, sm);
        const float ea = __expf(M + shift - mf);
        const float eb = __expf(sm - mf);
        N  = ea * N  + eb * sn;
        Dn = ea * Dn + eb * sd;
        M  = mf;
    }
}

__global__ void scan_pass3(const float* __restrict__ td,
                           const float* __restrict__ tfv)
{
    const int tid = blockIdx.x * blockDim.x + threadIdx.x;  // < NCH*NSEG
    const int d   = tid & (HID - 1);
    const int bs  = tid >> 11;
    const int seg = bs & (NSEG - 1);
    const int b   = bs >> 4;

    const float w  = -__expf(td[d]);
    const float tf = tfv[d];
    float num = g_pn[tid], den = g_pd[tid], mx = g_pm[tid];

    const size_t base = (size_t)(b * SEQ + seg * SEG) * HID + d;
    for (int i = 0; i < SEG; i++) {
        const size_t off = base + (size_t)i * HID;
        const float k = g_K[off];
        const float v = g_V[off];

        // output (current token boosted by time_first, pre-update state)
        const float mo  = fmaxf(mx, k + tf);
        const float o1  = __expf(mx - mo);
        const float o2  = __expf(k + tf - mo);
        const float out = (o1 * num + o2 * v) / (o1 * den + o2);

        // state update with decay
        const float mn = fmaxf(mx + w, k);
        const float e1 = __expf(mx + w - mn);
        const float e2 = __expf(k - mn);
        num = e1 * num + e2 * v;
        den = e1 * den + e2;
        mx  = mn;

        g_R[off] *= out;   // fuse r * wkv in place (GEMM2 input)
    }
}

// ---------------------------------------------------------------------------
// Launch. Input order (metadata): hidden, time_decay, time_first,
// time_mix_key, time_mix_value, time_mix_receptance, Wk, Wv, Wr, Wo.
// ---------------------------------------------------------------------------
extern "C" void kernel_launch(void* const* d_in, const int* in_sizes, int n_in,
                              void* d_out, int out_size)
{
    const float* hidden = (const float*)d_in[0];
    const float* td     = (const float*)d_in[1];
    const float* tf     = (const float*)d_in[2];
    const float* mk     = (const float*)d_in[3];
    const float* mv     = (const float*)d_in[4];
    const float* mr     = (const float*)d_in[5];
    const float* Wk     = (const float*)d_in[6];
    const float* Wv     = (const float*)d_in[7];
    const float* Wr     = (const float*)d_in[8];
    const float* Wo     = (const float*)d_in[9];
    float* out          = (float*)d_out;

    dim3 g1(HID / 128, MROWS / 128, 3);
    gemm_kvr<<<g1, 256>>>(hidden, Wk, Wv, Wr, mk, mv, mr);

    scan_pass1<<<(NCH * NSEG) / 256, 256>>>(td);
    scan_mid  <<<NCH / 256, 256>>>(td);
    scan_pass3<<<(NCH * NSEG) / 256, 256>>>(td, tf);

    dim3 g2(HID / 128, MROWS / 128, 1);
    gemm_o<<<g2, 256>>>(Wo, out);
}

// round 7
// speedup vs baseline: 2.9813x; 2.9813x over previous
#include <cuda_runtime.h>
#include <cuda_bf16.h>
#include <cstdint>
#include <math.h>

// Problem constants: B=4, S=2048, H=D=2048, fp32 I/O.
#define BATCH 4
#define SEQ   2048
#define HID   2048
#define MROWS (BATCH * SEQ)                 // 8192
#define MELEM ((size_t)MROWS * HID)         // 16,777,216
#define WELEM ((size_t)HID * HID)           // 4,194,304

// Segmented scan config
#define NSEG  32
#define SEG   (SEQ / NSEG)                  // 64
#define NCH   (BATCH * HID)                 // 8192

// ---------------------------------------------------------------------------
// Scratch (device globals; allocation is forbidden)
// ---------------------------------------------------------------------------
__device__ float g_K[MELEM];
__device__ float g_V[MELEM];
__device__ float g_R[MELEM];
__device__ __nv_bfloat16 g_Xhi[3 * MELEM];  // xk/xv/xr hi
__device__ __nv_bfloat16 g_Xlo[3 * MELEM];  // xk/xv/xr lo
__device__ __nv_bfloat16 g_Phi[MELEM];      // (r*wkv) hi
__device__ __nv_bfloat16 g_Plo[MELEM];      // (r*wkv) lo
__device__ __nv_bfloat16 g_Whi[4 * WELEM];  // Wk,Wv,Wr,Wo hi
__device__ __nv_bfloat16 g_Wlo[4 * WELEM];  // lo
__device__ float g_sn[NCH * NSEG], g_sd[NCH * NSEG], g_sm[NCH * NSEG];
__device__ float g_pn[NCH * NSEG], g_pd[NCH * NSEG], g_pm[NCH * NSEG];

// ---------------------------------------------------------------------------
// Helpers
// ---------------------------------------------------------------------------
__device__ __forceinline__ uint32_t smem_to_u32(const void* p) {
    uint32_t a;
    asm("{ .reg .u64 t; cvta.to.shared.u64 t, %1; cvt.u32.u64 %0, t; }"
        : "=r"(a) : "l"(p));
    return a;
}
__device__ __forceinline__ void cp16(uint32_t dst, const void* src) {
    uint64_t g = (uint64_t)__cvta_generic_to_global((void*)src);
    asm volatile("cp.async.cg.shared.global [%0], [%1], 16;" :: "r"(dst), "l"(g));
}
__device__ __forceinline__ void ldsm_x4(uint32_t addr, uint32_t* r) {
    asm volatile("ldmatrix.sync.aligned.m8n8.x4.shared.b16 {%0,%1,%2,%3}, [%4];"
                 : "=r"(r[0]), "=r"(r[1]), "=r"(r[2]), "=r"(r[3]) : "r"(addr));
}
__device__ __forceinline__ void mma_bf16(float* d, const uint32_t* a, const uint32_t* b) {
    asm volatile(
        "mma.sync.aligned.m16n8k16.row.col.f32.bf16.bf16.f32 "
        "{%0,%1,%2,%3}, {%4,%5,%6,%7}, {%8,%9}, {%0,%1,%2,%3};"
        : "+f"(d[0]), "+f"(d[1]), "+f"(d[2]), "+f"(d[3])
        : "r"(a[0]), "r"(a[1]), "r"(a[2]), "r"(a[3]), "r"(b[0]), "r"(b[1]));
}

// SMEM tile layout: 128 tile-rows x 32 bf16 (64B). Two tile-rows packed per
// 128B smem row; 16B chunk index XOR-swizzled by smem row for conflict-free
// cp.async stores AND ldmatrix reads.
__device__ __forceinline__ uint32_t swz(uint32_t row, uint32_t kc) {
    const uint32_t R = row >> 1;
    const uint32_t cidx = (((row & 1) << 2) | kc) ^ (R & 7);
    return R * 128 + cidx * 16;
}

// ---------------------------------------------------------------------------
// GEMM: C[m,n] = sum_k A[m,k]*B[n,k], K' = 3*2048 via compensated bf16 split
// (Ahi*Bhi + Alo*Bhi + Ahi*Blo). CTA 128x128, BK=32, 4 warps (64x64 tiles),
// 3-stage cp.async pipeline, m16n8k16 bf16 HMMA.
// ---------------------------------------------------------------------------
#define STAGES 3
#define STAGE_BYTES 16384            // A 8KB + B 8KB
#define GEMM_SMEM (STAGES * STAGE_BYTES)   // 48KB (no opt-in needed)
#define NIT 192                      // 3 passes * (2048/32)

__device__ __forceinline__ void load_stage(uint32_t sbase, int cn,
                                           const __nv_bfloat16* __restrict__ Ap,
                                           const __nv_bfloat16* __restrict__ Bp,
                                           int m0, int n0, int tid)
{
    const int kcol = (cn & 63) * 32;
#pragma unroll
    for (int i = 0; i < 4; i++) {
        const int ch = tid + i * 128;          // 0..511
        const int row = ch >> 2, c = ch & 3;
        const uint32_t so = swz(row, c);
        cp16(sbase + so,        Ap + (size_t)(m0 + row) * HID + kcol + c * 8);
        cp16(sbase + 8192 + so, Bp + (size_t)(n0 + row) * HID + kcol + c * 8);
    }
    asm volatile("cp.async.commit_group;" ::: "memory");
}

__device__ void gemm_core(const __nv_bfloat16* __restrict__ Ahi,
                          const __nv_bfloat16* __restrict__ Alo,
                          const __nv_bfloat16* __restrict__ Bhi,
                          const __nv_bfloat16* __restrict__ Blo,
                          float* __restrict__ C, bool sig)
{
    __shared__ char smem[GEMM_SMEM];
    const uint32_t sb = smem_to_u32(smem);
    const int tid = threadIdx.x;
    const int lane = tid & 31;
    const int wid = tid >> 5;
    const int wm = (wid & 1) * 64;             // warp M offset (2 warps)
    const int wn = (wid >> 1) * 64;            // warp N offset (2 warps)
    const int m0 = blockIdx.y * 128, n0 = blockIdx.x * 128;

    const __nv_bfloat16* Ap[3] = {Ahi, Alo, Ahi};
    const __nv_bfloat16* Bp[3] = {Bhi, Bhi, Blo};

    float acc[4][8][4];
#pragma unroll
    for (int i = 0; i < 4; i++)
#pragma unroll
        for (int j = 0; j < 8; j++)
#pragma unroll
            for (int q = 0; q < 4; q++) acc[i][j][q] = 0.f;

    // Precompute per-lane LDSM row/chunk components
    const int a_row = (lane & 15);             // + wm + mt*16
    const int a_kc  = (lane >> 4);             // + kf*2
    const int b_row = ((lane >> 4) << 3) + (lane & 7);   // + wn + np*16
    const int b_kc  = ((lane >> 3) & 1);       // + kf*2

    // prologue: stages 0,1
    load_stage(sb,               0, Ap[0], Bp[0], m0, n0, tid);
    load_stage(sb + STAGE_BYTES, 1, Ap[0], Bp[0], m0, n0, tid);

    for (int it = 0; it < NIT; ++it) {
        if (it < NIT - 1) asm volatile("cp.async.wait_group 1;" ::: "memory");
        else              asm volatile("cp.async.wait_group 0;" ::: "memory");
        __syncthreads();

        const int cn = it + 2;
        if (cn < NIT) {
            load_stage(sb + (cn % 3) * STAGE_BYTES, cn,
                       Ap[cn >> 6], Bp[cn >> 6], m0, n0, tid);
        }

        const uint32_t sA = sb + (it % 3) * STAGE_BYTES;
        const uint32_t sB = sA + 8192;

#pragma unroll
        for (int kf = 0; kf < 2; kf++) {
            uint32_t a[4][4], b[4][4];
#pragma unroll
            for (int mt = 0; mt < 4; mt++)
                ldsm_x4(sA + swz(wm + mt * 16 + a_row, kf * 2 + a_kc), a[mt]);
#pragma unroll
            for (int np = 0; np < 4; np++)
                ldsm_x4(sB + swz(wn + np * 16 + b_row, kf * 2 + b_kc), b[np]);
#pragma unroll
            for (int mt = 0; mt < 4; mt++)
#pragma unroll
                for (int nf = 0; nf < 8; nf++)
                    mma_bf16(acc[mt][nf], a[mt], &b[nf >> 1][(nf & 1) * 2]);
        }
    }

    // epilogue: direct register -> GMEM (float2 per fragment row)
#pragma unroll
    for (int mt = 0; mt < 4; mt++) {
        const int r0 = m0 + wm + mt * 16 + (lane >> 2);
#pragma unroll
        for (int nf = 0; nf < 8; nf++) {
            const int col = n0 + wn + nf * 8 + 2 * (lane & 3);
            float2 v0 = make_float2(acc[mt][nf][0], acc[mt][nf][1]);
            float2 v1 = make_float2(acc[mt][nf][2], acc[mt][nf][3]);
            if (sig) {
                v0.x = 1.f / (1.f + __expf(-v0.x));
                v0.y = 1.f / (1.f + __expf(-v0.y));
                v1.x = 1.f / (1.f + __expf(-v1.x));
                v1.y = 1.f / (1.f + __expf(-v1.y));
            }
            *reinterpret_cast<float2*>(C + (size_t)r0 * HID + col)       = v0;
            *reinterpret_cast<float2*>(C + (size_t)(r0 + 8) * HID + col) = v1;
        }
    }
}

__global__ __launch_bounds__(128)
void gemm_kvr()
{
    const int z = blockIdx.z;
    float* C = (z == 0) ? g_K : (z == 1) ? g_V : g_R;
    gemm_core(g_Xhi + (size_t)z * MELEM, g_Xlo + (size_t)z * MELEM,
              g_Whi + (size_t)z * WELEM, g_Wlo + (size_t)z * WELEM,
              C, z == 2);
}

__global__ __launch_bounds__(128)
void gemm_o(float* __restrict__ out)
{
    gemm_core(g_Phi, g_Plo, g_Whi + 3 * WELEM, g_Wlo + 3 * WELEM, out, false);
}

// ---------------------------------------------------------------------------
// Prep: bf16 hi/lo splits
// ---------------------------------------------------------------------------
__device__ __forceinline__ void split_store4(float a, float b, float c, float d,
                                             __nv_bfloat16* ph, __nv_bfloat16* pl)
{
    union { __nv_bfloat16 v[4]; uint2 u; } H, L;
    H.v[0] = __float2bfloat16_rn(a); L.v[0] = __float2bfloat16_rn(a - __bfloat162float(H.v[0]));
    H.v[1] = __float2bfloat16_rn(b); L.v[1] = __float2bfloat16_rn(b - __bfloat162float(H.v[1]));
    H.v[2] = __float2bfloat16_rn(c); L.v[2] = __float2bfloat16_rn(c - __bfloat162float(H.v[2]));
    H.v[3] = __float2bfloat16_rn(d); L.v[3] = __float2bfloat16_rn(d - __bfloat162float(H.v[3]));
    *reinterpret_cast<uint2*>(ph) = H.u;
    *reinterpret_cast<uint2*>(pl) = L.u;
}

__global__ __launch_bounds__(256)
void prep_w(const float* __restrict__ Wk, const float* __restrict__ Wv,
            const float* __restrict__ Wr, const float* __restrict__ Wo)
{
    const int y = blockIdx.y;
    const float* W = (y == 0) ? Wk : (y == 1) ? Wv : (y == 2) ? Wr : Wo;
    const size_t base = (size_t)y * WELEM;
    const size_t i4 = ((size_t)blockIdx.x * 256 + threadIdx.x) * 4;
    float4 w = *reinterpret_cast<const float4*>(W + i4);
    split_store4(w.x, w.y, w.z, w.w, g_Whi + base + i4, g_Wlo + base + i4);
}

__global__ __launch_bounds__(256)
void prep_act(const float* __restrict__ hidden, const float* __restrict__ mk,
              const float* __restrict__ mv, const float* __restrict__ mr)
{
    const size_t i4 = ((size_t)blockIdx.x * 256 + threadIdx.x) * 4;
    const int h = (int)(i4 & (HID - 1));
    const int s = (int)((i4 >> 11) & (SEQ - 1));
    const float4 cur = *reinterpret_cast<const float4*>(hidden + i4);
    float4 prv = make_float4(0.f, 0.f, 0.f, 0.f);
    if (s != 0) prv = *reinterpret_cast<const float4*>(hidden + i4 - HID);

    const float4 tk = *reinterpret_cast<const float4*>(mk + h);
    const float4 tv = *reinterpret_cast<const float4*>(mv + h);
    const float4 tr = *reinterpret_cast<const float4*>(mr + h);

    split_store4(fmaf(tk.x, cur.x - prv.x, prv.x), fmaf(tk.y, cur.y - prv.y, prv.y),
                 fmaf(tk.z, cur.z - prv.z, prv.z), fmaf(tk.w, cur.w - prv.w, prv.w),
                 g_Xhi + i4, g_Xlo + i4);
    split_store4(fmaf(tv.x, cur.x - prv.x, prv.x), fmaf(tv.y, cur.y - prv.y, prv.y),
                 fmaf(tv.z, cur.z - prv.z, prv.z), fmaf(tv.w, cur.w - prv.w, prv.w),
                 g_Xhi + MELEM + i4, g_Xlo + MELEM + i4);
    split_store4(fmaf(tr.x, cur.x - prv.x, prv.x), fmaf(tr.y, cur.y - prv.y, prv.y),
                 fmaf(tr.z, cur.z - prv.z, prv.z), fmaf(tr.w, cur.w - prv.w, prv.w),
                 g_Xhi + 2 * MELEM + i4, g_Xlo + 2 * MELEM + i4);
}

// ---------------------------------------------------------------------------
// WKV segmented scan (exp-stabilized linear recurrence -> associative)
// ---------------------------------------------------------------------------
__global__ void scan_pass1(const float* __restrict__ td)
{
    const int tid = blockIdx.x * blockDim.x + threadIdx.x;  // < NCH*NSEG
    const int d   = tid & (HID - 1);
    const int bs  = tid >> 11;
    const int seg = bs & (NSEG - 1);
    const int b   = bs >> 5;

    const float w = -__expf(td[d]);
    const size_t base = (size_t)(b * SEQ + seg * SEG) * HID + d;

    float num = 0.f, den = 0.f, mx = -1e38f;
#pragma unroll 4
    for (int i = 0; i < SEG; i++) {
        const size_t off = base + (size_t)i * HID;
        const float k = g_K[off];
        const float v = g_V[off];
        const float mn = fmaxf(mx + w, k);
        const float e1 = __expf(mx + w - mn);
        const float e2 = __expf(k - mn);
        num = e1 * num + e2 * v;
        den = e1 * den + e2;
        mx  = mn;
    }
    g_sn[tid] = num; g_sd[tid] = den; g_sm[tid] = mx;
}

__global__ void scan_mid(const float* __restrict__ td)
{
    const int tid = blockIdx.x * blockDim.x + threadIdx.x;  // < NCH
    const int d = tid & (HID - 1);
    const int b = tid >> 11;

    const float w = -__expf(td[d]);
    const float shift = w * (float)SEG;

    float N = 0.f, Dn = 0.f, M = -1e38f;
#pragma unroll
    for (int seg = 0; seg < NSEG; seg++) {
        const int idx = ((b * NSEG + seg) << 11) + d;
        g_pn[idx] = N; g_pd[idx] = Dn; g_pm[idx] = M;
        const float sn = g_sn[idx], sd = g_sd[idx], sm = g_sm[idx];
        const float mf = fmaxf(M + shift, sm);
        const float ea = __expf(M + shift - mf);
        const float eb = __expf(sm - mf);
        N  = ea * N  + eb * sn;
        Dn = ea * Dn + eb * sd;
        M  = mf;
    }
}

__global__ void scan_pass3(const float* __restrict__ td,
                           const float* __restrict__ tfv)
{
    const int tid = blockIdx.x * blockDim.x + threadIdx.x;  // < NCH*NSEG
    const int d   = tid & (HID - 1);
    const int bs  = tid >> 11;
    const int seg = bs & (NSEG - 1);
    const int b   = bs >> 5;

    const float w  = -__expf(td[d]);
    const float tf = tfv[d];
    float num = g_pn[tid], den = g_pd[tid], mx = g_pm[tid];

    const size_t base = (size_t)(b * SEQ + seg * SEG) * HID + d;
#pragma unroll 4
    for (int i = 0; i < SEG; i++) {
        const size_t off = base + (size_t)i * HID;
        const float k = g_K[off];
        const float v = g_V[off];

        const float mo  = fmaxf(mx, k + tf);
        const float o1  = __expf(mx - mo);
        const float o2  = __expf(k + tf - mo);
        const float out = (o1 * num + o2 * v) / (o1 * den + o2);

        const float mn = fmaxf(mx + w, k);
        const float e1 = __expf(mx + w - mn);
        const float e2 = __expf(k - mn);
        num = e1 * num + e2 * v;
        den = e1 * den + e2;
        mx  = mn;

        const float prod = g_R[off] * out;              // r * wkv
        const __nv_bfloat16 hi = __float2bfloat16_rn(prod);
        g_Phi[off] = hi;
        g_Plo[off] = __float2bfloat16_rn(prod - __bfloat162float(hi));
    }
}

// ---------------------------------------------------------------------------
// Launch. Input order: hidden, time_decay, time_first, time_mix_key,
// time_mix_value, time_mix_receptance, Wk, Wv, Wr, Wo.
// ---------------------------------------------------------------------------
extern "C" void kernel_launch(void* const* d_in, const int* in_sizes, int n_in,
                              void* d_out, int out_size)
{
    const float* hidden = (const float*)d_in[0];
    const float* td     = (const float*)d_in[1];
    const float* tf     = (const float*)d_in[2];
    const float* mk     = (const float*)d_in[3];
    const float* mv     = (const float*)d_in[4];
    const float* mr     = (const float*)d_in[5];
    const float* Wk     = (const float*)d_in[6];
    const float* Wv     = (const float*)d_in[7];
    const float* Wr     = (const float*)d_in[8];
    const float* Wo     = (const float*)d_in[9];
    float* out          = (float*)d_out;

    prep_w  <<<dim3(4096, 4), 256>>>(Wk, Wv, Wr, Wo);
    prep_act<<<16384, 256>>>(hidden, mk, mv, mr);

    gemm_kvr<<<dim3(HID / 128, MROWS / 128, 3), 128>>>();

    scan_pass1<<<(NCH * NSEG) / 256, 256>>>(td);
    scan_mid  <<<NCH / 256, 256>>>(td);
    scan_pass3<<<(NCH * NSEG) / 256, 256>>>(td, tf);

    gemm_o<<<dim3(HID / 128, MROWS / 128, 1), 128>>>(out);
}

// round 8
// speedup vs baseline: 4.0468x; 1.3574x over previous
#include <cuda_runtime.h>
#include <cuda_fp16.h>
#include <cstdint>
#include <math.h>

// Problem constants: B=4, S=2048, H=D=2048, fp32 I/O.
#define BATCH 4
#define SEQ   2048
#define HID   2048
#define MROWS (BATCH * SEQ)                 // 8192
#define MELEM ((size_t)MROWS * HID)         // 16,777,216
#define WELEM ((size_t)HID * HID)           // 4,194,304

// Segmented scan config
#define NSEG  32
#define SEG   (SEQ / NSEG)                  // 64
#define NCH   (BATCH * HID)                 // 8192

// ---------------------------------------------------------------------------
// Scratch (device globals; allocation is forbidden)
// ---------------------------------------------------------------------------
__device__ float g_K[MELEM];
__device__ float g_V[MELEM];
__device__ float g_R[MELEM];
__device__ __half g_Xhi[3 * MELEM];   // xk/xv/xr hi (fp16)
__device__ __half g_Xlo[3 * MELEM];   // xk/xv/xr lo (fp16)
__device__ __half g_Phi[MELEM];       // (r*wkv) hi
__device__ __half g_Plo[MELEM];       // (r*wkv) lo
__device__ __half g_Whi[4 * WELEM];   // Wk,Wv,Wr,Wo hi (fp16; no lo needed)
__device__ float g_sn[NCH * NSEG], g_sd[NCH * NSEG], g_sm[NCH * NSEG];
__device__ float g_pn[NCH * NSEG], g_pd[NCH * NSEG], g_pm[NCH * NSEG];

// ---------------------------------------------------------------------------
// Helpers
// ---------------------------------------------------------------------------
__device__ __forceinline__ uint32_t smem_to_u32(const void* p) {
    uint32_t a;
    asm("{ .reg .u64 t; cvta.to.shared.u64 t, %1; cvt.u32.u64 %0, t; }"
        : "=r"(a) : "l"(p));
    return a;
}
__device__ __forceinline__ void cp16(uint32_t dst, const void* src) {
    uint64_t g = (uint64_t)__cvta_generic_to_global((void*)src);
    asm volatile("cp.async.cg.shared.global [%0], [%1], 16;" :: "r"(dst), "l"(g));
}
__device__ __forceinline__ void ldsm_x4(uint32_t addr, uint32_t* r) {
    asm volatile("ldmatrix.sync.aligned.m8n8.x4.shared.b16 {%0,%1,%2,%3}, [%4];"
                 : "=r"(r[0]), "=r"(r[1]), "=r"(r[2]), "=r"(r[3]) : "r"(addr));
}
__device__ __forceinline__ void mma_f16(float* d, const uint32_t* a, const uint32_t* b) {
    asm volatile(
        "mma.sync.aligned.m16n8k16.row.col.f32.f16.f16.f32 "
        "{%0,%1,%2,%3}, {%4,%5,%6,%7}, {%8,%9}, {%0,%1,%2,%3};"
        : "+f"(d[0]), "+f"(d[1]), "+f"(d[2]), "+f"(d[3])
        : "r"(a[0]), "r"(a[1]), "r"(a[2]), "r"(a[3]), "r"(b[0]), "r"(b[1]));
}

// SMEM tile layout: 128 tile-rows x 32 fp16 (64B). Two tile-rows packed per
// 128B smem row; 16B chunk index XOR-swizzled by smem row for conflict-free
// cp.async stores AND ldmatrix reads.
__device__ __forceinline__ uint32_t swz(uint32_t row, uint32_t kc) {
    const uint32_t R = row >> 1;
    const uint32_t cidx = (((row & 1) << 2) | kc) ^ (R & 7);
    return R * 128 + cidx * 16;
}

// ---------------------------------------------------------------------------
// GEMM: C[m,n] = sum_k A[m,k]*B[n,k], K' = 2*2048 via compensated fp16 split:
// A_hi*B_hi + A_lo*B_hi = A*B_hi (dropped term A*B_lo ~ 2^-12 relative).
// CTA 128x128, BK=32, 4 warps (64x64 tiles), 3-stage cp.async pipeline,
// m16n8k16 fp16 HMMA.
// ---------------------------------------------------------------------------
#define STAGES 3
#define STAGE_BYTES 16384            // A 8KB + B 8KB
#define GEMM_SMEM (STAGES * STAGE_BYTES)   // 48KB
#define NIT 128                      // 2 passes * (2048/32)

__device__ __forceinline__ void load_stage(uint32_t sbase, int cn,
                                           const __half* __restrict__ Ap,
                                           const __half* __restrict__ Bp,
                                           int m0, int n0, int tid)
{
    const int kcol = (cn & 63) * 32;
#pragma unroll
    for (int i = 0; i < 4; i++) {
        const int ch = tid + i * 128;          // 0..511
        const int row = ch >> 2, c = ch & 3;
        const uint32_t so = swz(row, c);
        cp16(sbase + so,        Ap + (size_t)(m0 + row) * HID + kcol + c * 8);
        cp16(sbase + 8192 + so, Bp + (size_t)(n0 + row) * HID + kcol + c * 8);
    }
    asm volatile("cp.async.commit_group;" ::: "memory");
}

__device__ void gemm_core(const __half* __restrict__ Ahi,
                          const __half* __restrict__ Alo,
                          const __half* __restrict__ Bhi,
                          float* __restrict__ C, bool sig)
{
    __shared__ char smem[GEMM_SMEM];
    const uint32_t sb = smem_to_u32(smem);
    const int tid = threadIdx.x;
    const int lane = tid & 31;
    const int wid = tid >> 5;
    const int wm = (wid & 1) * 64;             // warp M offset
    const int wn = (wid >> 1) * 64;            // warp N offset
    const int m0 = blockIdx.y * 128, n0 = blockIdx.x * 128;

    const __half* Ap[2] = {Ahi, Alo};

    float acc[4][8][4];
#pragma unroll
    for (int i = 0; i < 4; i++)
#pragma unroll
        for (int j = 0; j < 8; j++)
#pragma unroll
            for (int q = 0; q < 4; q++) acc[i][j][q] = 0.f;

    // Per-lane LDSM row/chunk components
    const int a_row = (lane & 15);
    const int a_kc  = (lane >> 4);
    const int b_row = ((lane >> 4) << 3) + (lane & 7);
    const int b_kc  = ((lane >> 3) & 1);

    // prologue: stages 0,1
    load_stage(sb,               0, Ap[0], Bhi, m0, n0, tid);
    load_stage(sb + STAGE_BYTES, 1, Ap[0], Bhi, m0, n0, tid);

    for (int it = 0; it < NIT; ++it) {
        if (it < NIT - 1) asm volatile("cp.async.wait_group 1;" ::: "memory");
        else              asm volatile("cp.async.wait_group 0;" ::: "memory");
        __syncthreads();

        const int cn = it + 2;
        if (cn < NIT) {
            load_stage(sb + (cn % 3) * STAGE_BYTES, cn,
                       Ap[cn >> 6], Bhi, m0, n0, tid);
        }

        const uint32_t sA = sb + (it % 3) * STAGE_BYTES;
        const uint32_t sB = sA + 8192;

#pragma unroll
        for (int kf = 0; kf < 2; kf++) {
            uint32_t a[4][4], b[4][4];
#pragma unroll
            for (int mt = 0; mt < 4; mt++)
                ldsm_x4(sA + swz(wm + mt * 16 + a_row, kf * 2 + a_kc), a[mt]);
#pragma unroll
            for (int np = 0; np < 4; np++)
                ldsm_x4(sB + swz(wn + np * 16 + b_row, kf * 2 + b_kc), b[np]);
#pragma unroll
            for (int mt = 0; mt < 4; mt++)
#pragma unroll
                for (int nf = 0; nf < 8; nf++)
                    mma_f16(acc[mt][nf], a[mt], &b[nf >> 1][(nf & 1) * 2]);
        }
    }

    // epilogue: direct register -> GMEM
#pragma unroll
    for (int mt = 0; mt < 4; mt++) {
        const int r0 = m0 + wm + mt * 16 + (lane >> 2);
#pragma unroll
        for (int nf = 0; nf < 8; nf++) {
            const int col = n0 + wn + nf * 8 + 2 * (lane & 3);
            float2 v0 = make_float2(acc[mt][nf][0], acc[mt][nf][1]);
            float2 v1 = make_float2(acc[mt][nf][2], acc[mt][nf][3]);
            if (sig) {
                v0.x = 1.f / (1.f + __expf(-v0.x));
                v0.y = 1.f / (1.f + __expf(-v0.y));
                v1.x = 1.f / (1.f + __expf(-v1.x));
                v1.y = 1.f / (1.f + __expf(-v1.y));
            }
            *reinterpret_cast<float2*>(C + (size_t)r0 * HID + col)       = v0;
            *reinterpret_cast<float2*>(C + (size_t)(r0 + 8) * HID + col) = v1;
        }
    }
}

__global__ __launch_bounds__(128)
void gemm_kvr()
{
    const int z = blockIdx.z;
    float* C = (z == 0) ? g_K : (z == 1) ? g_V : g_R;
    gemm_core(g_Xhi + (size_t)z * MELEM, g_Xlo + (size_t)z * MELEM,
              g_Whi + (size_t)z * WELEM, C, z == 2);
}

__global__ __launch_bounds__(128)
void gemm_o(float* __restrict__ out)
{
    gemm_core(g_Phi, g_Plo, g_Whi + 3 * WELEM, out, false);
}

// ---------------------------------------------------------------------------
// Prep: fp16 hi/lo splits
// ---------------------------------------------------------------------------
__device__ __forceinline__ void split_store4(float a, float b, float c, float d,
                                             __half* ph, __half* pl)
{
    union { __half v[4]; uint2 u; } H, L;
    H.v[0] = __float2half_rn(a); L.v[0] = __float2half_rn(a - __half2float(H.v[0]));
    H.v[1] = __float2half_rn(b); L.v[1] = __float2half_rn(b - __half2float(H.v[1]));
    H.v[2] = __float2half_rn(c); L.v[2] = __float2half_rn(c - __half2float(H.v[2]));
    H.v[3] = __float2half_rn(d); L.v[3] = __float2half_rn(d - __half2float(H.v[3]));
    *reinterpret_cast<uint2*>(ph) = H.u;
    *reinterpret_cast<uint2*>(pl) = L.u;
}

__global__ __launch_bounds__(256)
void prep_w(const float* __restrict__ Wk, const float* __restrict__ Wv,
            const float* __restrict__ Wr, const float* __restrict__ Wo)
{
    const int y = blockIdx.y;
    const float* W = (y == 0) ? Wk : (y == 1) ? Wv : (y == 2) ? Wr : Wo;
    const size_t base = (size_t)y * WELEM;
    const size_t i4 = ((size_t)blockIdx.x * 256 + threadIdx.x) * 4;
    float4 w = *reinterpret_cast<const float4*>(W + i4);
    union { __half v[4]; uint2 u; } H;
    H.v[0] = __float2half_rn(w.x);
    H.v[1] = __float2half_rn(w.y);
    H.v[2] = __float2half_rn(w.z);
    H.v[3] = __float2half_rn(w.w);
    *reinterpret_cast<uint2*>(g_Whi + base + i4) = H.u;
}

__global__ __launch_bounds__(256)
void prep_act(const float* __restrict__ hidden, const float* __restrict__ mk,
              const float* __restrict__ mv, const float* __restrict__ mr)
{
    const size_t i4 = ((size_t)blockIdx.x * 256 + threadIdx.x) * 4;
    const int h = (int)(i4 & (HID - 1));
    const int s = (int)((i4 >> 11) & (SEQ - 1));
    const float4 cur = *reinterpret_cast<const float4*>(hidden + i4);
    float4 prv = make_float4(0.f, 0.f, 0.f, 0.f);
    if (s != 0) prv = *reinterpret_cast<const float4*>(hidden + i4 - HID);

    const float4 tk = *reinterpret_cast<const float4*>(mk + h);
    const float4 tv = *reinterpret_cast<const float4*>(mv + h);
    const float4 tr = *reinterpret_cast<const float4*>(mr + h);

    split_store4(fmaf(tk.x, cur.x - prv.x, prv.x), fmaf(tk.y, cur.y - prv.y, prv.y),
                 fmaf(tk.z, cur.z - prv.z, prv.z), fmaf(tk.w, cur.w - prv.w, prv.w),
                 g_Xhi + i4, g_Xlo + i4);
    split_store4(fmaf(tv.x, cur.x - prv.x, prv.x), fmaf(tv.y, cur.y - prv.y, prv.y),
                 fmaf(tv.z, cur.z - prv.z, prv.z), fmaf(tv.w, cur.w - prv.w, prv.w),
                 g_Xhi + MELEM + i4, g_Xlo + MELEM + i4);
    split_store4(fmaf(tr.x, cur.x - prv.x, prv.x), fmaf(tr.y, cur.y - prv.y, prv.y),
                 fmaf(tr.z, cur.z - prv.z, prv.z), fmaf(tr.w, cur.w - prv.w, prv.w),
                 g_Xhi + 2 * MELEM + i4, g_Xlo + 2 * MELEM + i4);
}

// ---------------------------------------------------------------------------
// WKV segmented scan (exp-stabilized linear recurrence -> associative)
// ---------------------------------------------------------------------------
__global__ void scan_pass1(const float* __restrict__ td)
{
    const int tid = blockIdx.x * blockDim.x + threadIdx.x;  // < NCH*NSEG
    const int d   = tid & (HID - 1);
    const int bs  = tid >> 11;
    const int seg = bs & (NSEG - 1);
    const int b   = bs >> 5;

    const float w = -__expf(td[d]);
    const size_t base = (size_t)(b * SEQ + seg * SEG) * HID + d;

    float num = 0.f, den = 0.f, mx = -1e38f;
#pragma unroll 4
    for (int i = 0; i < SEG; i++) {
        const size_t off = base + (size_t)i * HID;
        const float k = g_K[off];
        const float v = g_V[off];
        const float mn = fmaxf(mx + w, k);
        const float e1 = __expf(mx + w - mn);
        const float e2 = __expf(k - mn);
        num = e1 * num + e2 * v;
        den = e1 * den + e2;
        mx  = mn;
    }
    g_sn[tid] = num; g_sd[tid] = den; g_sm[tid] = mx;
}

__global__ void scan_mid(const float* __restrict__ td)
{
    const int tid = blockIdx.x * blockDim.x + threadIdx.x;  // < NCH
    const int d = tid & (HID - 1);
    const int b = tid >> 11;

    const float w = -__expf(td[d]);
    const float shift = w * (float)SEG;

    float N = 0.f, Dn = 0.f, M = -1e38f;
#pragma unroll
    for (int seg = 0; seg < NSEG; seg++) {
        const int idx = ((b * NSEG + seg) << 11) + d;
        g_pn[idx] = N; g_pd[idx] = Dn; g_pm[idx] = M;
        const float sn = g_sn[idx], sd = g_sd[idx], sm = g_sm[idx];
        const float mf = fmaxf(M + shift, sm);
        const float ea = __expf(M + shift - mf);
        const float eb = __expf(sm - mf);
        N  = ea * N  + eb * sn;
        Dn = ea * Dn + eb * sd;
        M  = mf;
    }
}

__global__ void scan_pass3(const float* __restrict__ td,
                           const float* __restrict__ tfv)
{
    const int tid = blockIdx.x * blockDim.x + threadIdx.x;  // < NCH*NSEG
    const int d   = tid & (HID - 1);
    const int bs  = tid >> 11;
    const int seg = bs & (NSEG - 1);
    const int b   = bs >> 5;

    const float w  = -__expf(td[d]);
    const float tf = tfv[d];
    float num = g_pn[tid], den = g_pd[tid], mx = g_pm[tid];

    const size_t base = (size_t)(b * SEQ + seg * SEG) * HID + d;
#pragma unroll 4
    for (int i = 0; i < SEG; i++) {
        const size_t off = base + (size_t)i * HID;
        const float k = g_K[off];
        const float v = g_V[off];

        const float mo  = fmaxf(mx, k + tf);
        const float o1  = __expf(mx - mo);
        const float o2  = __expf(k + tf - mo);
        const float out = (o1 * num + o2 * v) / (o1 * den + o2);

        const float mn = fmaxf(mx + w, k);
        const float e1 = __expf(mx + w - mn);
        const float e2 = __expf(k - mn);
        num = e1 * num + e2 * v;
        den = e1 * den + e2;
        mx  = mn;

        const float prod = g_R[off] * out;              // r * wkv
        const __half hi = __float2half_rn(prod);
        g_Phi[off] = hi;
        g_Plo[off] = __float2half_rn(prod - __half2float(hi));
    }
}

// ---------------------------------------------------------------------------
// Launch. Input order: hidden, time_decay, time_first, time_mix_key,
// time_mix_value, time_mix_receptance, Wk, Wv, Wr, Wo.
// ---------------------------------------------------------------------------
extern "C" void kernel_launch(void* const* d_in, const int* in_sizes, int n_in,
                              void* d_out, int out_size)
{
    const float* hidden = (const float*)d_in[0];
    const float* td     = (const float*)d_in[1];
    const float* tf     = (const float*)d_in[2];
    const float* mk     = (const float*)d_in[3];
    const float* mv     = (const float*)d_in[4];
    const float* mr     = (const float*)d_in[5];
    const float* Wk     = (const float*)d_in[6];
    const float* Wv     = (const float*)d_in[7];
    const float* Wr     = (const float*)d_in[8];
    const float* Wo     = (const float*)d_in[9];
    float* out          = (float*)d_out;

    prep_w  <<<dim3(4096, 4), 256>>>(Wk, Wv, Wr, Wo);
    prep_act<<<16384, 256>>>(hidden, mk, mv, mr);

    gemm_kvr<<<dim3(HID / 128, MROWS / 128, 3), 128>>>();

    scan_pass1<<<(NCH * NSEG) / 256, 256>>>(td);
    scan_mid  <<<NCH / 256, 256>>>(td);
    scan_pass3<<<(NCH * NSEG) / 256, 256>>>(td, tf);

    gemm_o<<<dim3(HID / 128, MROWS / 128, 1), 128>>>(out);
}

// round 10
// speedup vs baseline: 4.3394x; 1.0723x over previous
#include <cuda_runtime.h>
#include <cuda_fp16.h>
#include <cstdint>
#include <math.h>

// Problem constants: B=4, S=2048, H=D=2048, fp32 I/O.
#define BATCH 4
#define SEQ   2048
#define HID   2048
#define MROWS (BATCH * SEQ)                 // 8192
#define MELEM ((size_t)MROWS * HID)         // 16,777,216
#define WELEM ((size_t)HID * HID)           // 4,194,304

// Segmented scan config
#define NSEG  32
#define SEG   (SEQ / NSEG)                  // 64
#define NCH   (BATCH * HID)                 // 8192

// ---------------------------------------------------------------------------
// Scratch (device globals; allocation is forbidden)
// ---------------------------------------------------------------------------
__device__ float g_K[MELEM];
__device__ float g_V[MELEM];
__device__ float g_R[MELEM];
__device__ __half g_Xhi[3 * MELEM];   // xk/xv/xr hi (fp16)
__device__ __half g_Xlo[3 * MELEM];   // xk/xv/xr lo (fp16)
__device__ __half g_Phi[MELEM];       // (r*wkv) hi
__device__ __half g_Plo[MELEM];       // (r*wkv) lo
__device__ __half g_Whi[4 * WELEM];   // Wk,Wv,Wr,Wo hi (fp16; no lo needed)
__device__ float g_sn[NCH * NSEG], g_sd[NCH * NSEG], g_sm[NCH * NSEG];
__device__ float g_pn[NCH * NSEG], g_pd[NCH * NSEG], g_pm[NCH * NSEG];

// ---------------------------------------------------------------------------
// Helpers
// ---------------------------------------------------------------------------
__device__ __forceinline__ uint32_t smem_to_u32(const void* p) {
    uint32_t a;
    asm("{ .reg .u64 t; cvta.to.shared.u64 t, %1; cvt.u32.u64 %0, t; }"
        : "=r"(a) : "l"(p));
    return a;
}
__device__ __forceinline__ void cp16(uint32_t dst, const void* src) {
    uint64_t g = (uint64_t)__cvta_generic_to_global((void*)src);
    asm volatile("cp.async.cg.shared.global [%0], [%1], 16;" :: "r"(dst), "l"(g));
}
__device__ __forceinline__ void ldsm_x4(uint32_t addr, uint32_t* r) {
    asm volatile("ldmatrix.sync.aligned.m8n8.x4.shared.b16 {%0,%1,%2,%3}, [%4];"
                 : "=r"(r[0]), "=r"(r[1]), "=r"(r[2]), "=r"(r[3]) : "r"(addr));
}
__device__ __forceinline__ void mma_f16(float* d, const uint32_t* a, const uint32_t* b) {
    asm volatile(
        "mma.sync.aligned.m16n8k16.row.col.f32.f16.f16.f32 "
        "{%0,%1,%2,%3}, {%4,%5,%6,%7}, {%8,%9}, {%0,%1,%2,%3};"
        : "+f"(d[0]), "+f"(d[1]), "+f"(d[2]), "+f"(d[3])
        : "r"(a[0]), "r"(a[1]), "r"(a[2]), "r"(a[3]), "r"(b[0]), "r"(b[1]));
}

// SMEM tile layout: 128 tile-rows x 32 fp16 (64B). Two tile-rows packed per
// 128B smem row; 16B chunk index XOR-swizzled by smem row for conflict-free
// cp.async stores AND ldmatrix reads.
__device__ __forceinline__ uint32_t swz(uint32_t row, uint32_t kc) {
    const uint32_t R = row >> 1;
    const uint32_t cidx = (((row & 1) << 2) | kc) ^ (R & 7);
    return R * 128 + cidx * 16;
}

// ---------------------------------------------------------------------------
// GEMM: C[m,n] = sum_k (Ahi[m,k]+Alo[m,k]) * B[n,k], single fused K-sweep.
// fp16 compensated split: dropped term A*B_lo ~ 2^-12 relative.
// CTA 128x128, BK=32, 4 warps (64x64 tiles), 3-stage cp.async pipeline,
// each stage holds {Ahi 8KB, Alo 8KB, B 8KB}; B fragments are reused for
// both hi and lo MMAs (halves B smem/L2 traffic vs two passes).
// ---------------------------------------------------------------------------
#define STAGE_BYTES 24576            // Ahi 8KB + Alo 8KB + B 8KB
#define GEMM_SMEM (3 * STAGE_BYTES)  // 72KB (dynamic, opt-in)
#define NIT 64                       // 2048 / 32

__device__ __forceinline__ void load_stage(uint32_t sbase, int cn,
                                           const __half* __restrict__ Ahi,
                                           const __half* __restrict__ Alo,
                                           const __half* __restrict__ Bp,
                                           int m0, int n0, int tid)
{
    const int kcol = cn * 32;
#pragma unroll
    for (int i = 0; i < 4; i++) {
        const int ch = tid + i * 128;          // 0..511
        const int row = ch >> 2, c = ch & 3;
        const uint32_t so = swz(row, c);
        const size_t goff = (size_t)(m0 + row) * HID + kcol + c * 8;
        cp16(sbase + so,         Ahi + goff);
        cp16(sbase + 8192 + so,  Alo + goff);
        cp16(sbase + 16384 + so, Bp + (size_t)(n0 + row) * HID + kcol + c * 8);
    }
    asm volatile("cp.async.commit_group;" ::: "memory");
}

__device__ void gemm_core(const __half* __restrict__ Ahi,
                          const __half* __restrict__ Alo,
                          const __half* __restrict__ Bhi,
                          float* __restrict__ C, bool sig)
{
    extern __shared__ char smem[];
    const uint32_t sb = smem_to_u32(smem);
    const int tid = threadIdx.x;
    const int lane = tid & 31;
    const int wid = tid >> 5;
    const int wm = (wid & 1) * 64;             // warp M offset
    const int wn = (wid >> 1) * 64;            // warp N offset
    const int m0 = blockIdx.y * 128, n0 = blockIdx.x * 128;

    float acc[4][8][4];
#pragma unroll
    for (int i = 0; i < 4; i++)
#pragma unroll
        for (int j = 0; j < 8; j++)
#pragma unroll
            for (int q = 0; q < 4; q++) acc[i][j][q] = 0.f;

    // Per-lane LDSM row/chunk components
    const int a_row = (lane & 15);
    const int a_kc  = (lane >> 4);
    const int b_row = ((lane >> 4) << 3) + (lane & 7);
    const int b_kc  = ((lane >> 3) & 1);

    // prologue: stages 0,1
    load_stage(sb,               0, Ahi, Alo, Bhi, m0, n0, tid);
    load_stage(sb + STAGE_BYTES, 1, Ahi, Alo, Bhi, m0, n0, tid);

    for (int it = 0; it < NIT; ++it) {
        if (it < NIT - 1) asm volatile("cp.async.wait_group 1;" ::: "memory");
        else              asm volatile("cp.async.wait_group 0;" ::: "memory");
        __syncthreads();

        const int cn = it + 2;
        if (cn < NIT)
            load_stage(sb + (cn % 3) * STAGE_BYTES, cn, Ahi, Alo, Bhi, m0, n0, tid);

        const uint32_t sA  = sb + (it % 3) * STAGE_BYTES;
        const uint32_t sAl = sA + 8192;
        const uint32_t sB  = sA + 16384;

#pragma unroll
        for (int kf = 0; kf < 2; kf++) {
            uint32_t ah[4][4], al[4][4], b[4][4];
#pragma unroll
            for (int mt = 0; mt < 4; mt++) {
                const uint32_t so = swz(wm + mt * 16 + a_row, kf * 2 + a_kc);
                ldsm_x4(sA + so,  ah[mt]);
                ldsm_x4(sAl + so, al[mt]);
            }
#pragma unroll
            for (int np = 0; np < 4; np++)
                ldsm_x4(sB + swz(wn + np * 16 + b_row, kf * 2 + b_kc), b[np]);
#pragma unroll
            for (int mt = 0; mt < 4; mt++)
#pragma unroll
                for (int nf = 0; nf < 8; nf++) {
                    mma_f16(acc[mt][nf], ah[mt], &b[nf >> 1][(nf & 1) * 2]);
                    mma_f16(acc[mt][nf], al[mt], &b[nf >> 1][(nf & 1) * 2]);
                }
        }
    }

    // epilogue: direct register -> GMEM
#pragma unroll
    for (int mt = 0; mt < 4; mt++) {
        const int r0 = m0 + wm + mt * 16 + (lane >> 2);
#pragma unroll
        for (int nf = 0; nf < 8; nf++) {
            const int col = n0 + wn + nf * 8 + 2 * (lane & 3);
            float2 v0 = make_float2(acc[mt][nf][0], acc[mt][nf][1]);
            float2 v1 = make_float2(acc[mt][nf][2], acc[mt][nf][3]);
            if (sig) {
                v0.x = 1.f / (1.f + __expf(-v0.x));
                v0.y = 1.f / (1.f + __expf(-v0.y));
                v1.x = 1.f / (1.f + __expf(-v1.x));
                v1.y = 1.f / (1.f + __expf(-v1.y));
            }
            *reinterpret_cast<float2*>(C + (size_t)r0 * HID + col)       = v0;
            *reinterpret_cast<float2*>(C + (size_t)(r0 + 8) * HID + col) = v1;
        }
    }
}

__global__ __launch_bounds__(128)
void gemm_kvr()
{
    const int z = blockIdx.z;
    float* C = (z == 0) ? g_K : (z == 1) ? g_V : g_R;
    gemm_core(g_Xhi + (size_t)z * MELEM, g_Xlo + (size_t)z * MELEM,
              g_Whi + (size_t)z * WELEM, C, z == 2);
}

__global__ __launch_bounds__(128)
void gemm_o(float* __restrict__ out)
{
    gemm_core(g_Phi, g_Plo, g_Whi + 3 * WELEM, out, false);
}

// ---------------------------------------------------------------------------
// Prep: fp16 hi/lo splits
// ---------------------------------------------------------------------------
__device__ __forceinline__ void split_store4(float a, float b, float c, float d,
                                             __half* ph, __half* pl)
{
    union { __half v[4]; uint2 u; } H, L;
    H.v[0] = __float2half_rn(a); L.v[0] = __float2half_rn(a - __half2float(H.v[0]));
    H.v[1] = __float2half_rn(b); L.v[1] = __float2half_rn(b - __half2float(H.v[1]));
    H.v[2] = __float2half_rn(c); L.v[2] = __float2half_rn(c - __half2float(H.v[2]));
    H.v[3] = __float2half_rn(d); L.v[3] = __float2half_rn(d - __half2float(H.v[3]));
    *reinterpret_cast<uint2*>(ph) = H.u;
    *reinterpret_cast<uint2*>(pl) = L.u;
}

__global__ __launch_bounds__(256)
void prep_w(const float* __restrict__ Wk, const float* __restrict__ Wv,
            const float* __restrict__ Wr, const float* __restrict__ Wo)
{
    const int y = blockIdx.y;
    const float* W = (y == 0) ? Wk : (y == 1) ? Wv : (y == 2) ? Wr : Wo;
    const size_t base = (size_t)y * WELEM;
    const size_t i4 = ((size_t)blockIdx.x * 256 + threadIdx.x) * 4;
    float4 w = *reinterpret_cast<const float4*>(W + i4);
    union { __half v[4]; uint2 u; } H;
    H.v[0] = __float2half_rn(w.x);
    H.v[1] = __float2half_rn(w.y);
    H.v[2] = __float2half_rn(w.z);
    H.v[3] = __float2half_rn(w.w);
    *reinterpret_cast<uint2*>(g_Whi + base + i4) = H.u;
}

__global__ __launch_bounds__(256)
void prep_act(const float* __restrict__ hidden, const float* __restrict__ mk,
              const float* __restrict__ mv, const float* __restrict__ mr)
{
    const size_t i4 = ((size_t)blockIdx.x * 256 + threadIdx.x) * 4;
    const int h = (int)(i4 & (HID - 1));
    const int s = (int)((i4 >> 11) & (SEQ - 1));
    const float4 cur = *reinterpret_cast<const float4*>(hidden + i4);
    float4 prv = make_float4(0.f, 0.f, 0.f, 0.f);
    if (s != 0) prv = *reinterpret_cast<const float4*>(hidden + i4 - HID);

    const float4 tk = *reinterpret_cast<const float4*>(mk + h);
    const float4 tv = *reinterpret_cast<const float4*>(mv + h);
    const float4 tr = *reinterpret_cast<const float4*>(mr + h);

    split_store4(fmaf(tk.x, cur.x - prv.x, prv.x), fmaf(tk.y, cur.y - prv.y, prv.y),
                 fmaf(tk.z, cur.z - prv.z, prv.z), fmaf(tk.w, cur.w - prv.w, prv.w),
                 g_Xhi + i4, g_Xlo + i4);
    split_store4(fmaf(tv.x, cur.x - prv.x, prv.x), fmaf(tv.y, cur.y - prv.y, prv.y),
                 fmaf(tv.z, cur.z - prv.z, prv.z), fmaf(tv.w, cur.w - prv.w, prv.w),
                 g_Xhi + MELEM + i4, g_Xlo + MELEM + i4);
    split_store4(fmaf(tr.x, cur.x - prv.x, prv.x), fmaf(tr.y, cur.y - prv.y, prv.y),
                 fmaf(tr.z, cur.z - prv.z, prv.z), fmaf(tr.w, cur.w - prv.w, prv.w),
                 g_Xhi + 2 * MELEM + i4, g_Xlo + 2 * MELEM + i4);
}

// ---------------------------------------------------------------------------
// WKV segmented scan (exp-stabilized linear recurrence -> associative)
// ---------------------------------------------------------------------------
__global__ void scan_pass1(const float* __restrict__ td)
{
    const int tid = blockIdx.x * blockDim.x + threadIdx.x;  // < NCH*NSEG
    const int d   = tid & (HID - 1);
    const int bs  = tid >> 11;
    const int seg = bs & (NSEG - 1);
    const int b   = bs >> 5;

    const float w = -__expf(td[d]);
    const size_t base = (size_t)(b * SEQ + seg * SEG) * HID + d;

    float num = 0.f, den = 0.f, mx = -1e38f;
#pragma unroll 4
    for (int i = 0; i < SEG; i++) {
        const size_t off = base + (size_t)i * HID;
        const float k = g_K[off];
        const float v = g_V[off];
        const float mn = fmaxf(mx + w, k);
        const float e1 = __expf(mx + w - mn);
        const float e2 = __expf(k - mn);
        num = e1 * num + e2 * v;
        den = e1 * den + e2;
        mx  = mn;
    }
    g_sn[tid] = num; g_sd[tid] = den; g_sm[tid] = mx;
}

__global__ void scan_mid(const float* __restrict__ td)
{
    const int tid = blockIdx.x * blockDim.x + threadIdx.x;  // < NCH
    const int d = tid & (HID - 1);
    const int b = tid >> 11;

    const float w = -__expf(td[d]);
    const float shift = w * (float)SEG;

    float N = 0.f, Dn = 0.f, M = -1e38f;
#pragma unroll
    for (int seg = 0; seg < NSEG; seg++) {
        const int idx = ((b * NSEG + seg) << 11) + d;
        g_pn[idx] = N; g_pd[idx] = Dn; g_pm[idx] = M;
        const float sn = g_sn[idx], sd = g_sd[idx], sm = g_sm[idx];
        const float mf = fmaxf(M + shift, sm);
        const float ea = __expf(M + shift - mf);
        const float eb = __expf(sm - mf);
        N  = ea * N  + eb * sn;
        Dn = ea * Dn + eb * sd;
        M  = mf;
    }
}

__global__ void scan_pass3(const float* __restrict__ td,
                           const float* __restrict__ tfv)
{
    const int tid = blockIdx.x * blockDim.x + threadIdx.x;  // < NCH*NSEG
    const int d   = tid & (HID - 1);
    const int bs  = tid >> 11;
    const int seg = bs & (NSEG - 1);
    const int b   = bs >> 5;

    const float w  = -__expf(td[d]);
    const float tf = tfv[d];
    float num = g_pn[tid], den = g_pd[tid], mx = g_pm[tid];

    const size_t base = (size_t)(b * SEQ + seg * SEG) * HID + d;
#pragma unroll 4
    for (int i = 0; i < SEG; i++) {
        const size_t off = base + (size_t)i * HID;
        const float k = g_K[off];
        const float v = g_V[off];

        const float mo  = fmaxf(mx, k + tf);
        const float o1  = __expf(mx - mo);
        const float o2  = __expf(k + tf - mo);
        const float out = (o1 * num + o2 * v) / (o1 * den + o2);

        const float mn = fmaxf(mx + w, k);
        const float e1 = __expf(mx + w - mn);
        const float e2 = __expf(k - mn);
        num = e1 * num + e2 * v;
        den = e1 * den + e2;
        mx  = mn;

        const float prod = g_R[off] * out;              // r * wkv
        const __half hi = __float2half_rn(prod);
        g_Phi[off] = hi;
        g_Plo[off] = __float2half_rn(prod - __half2float(hi));
    }
}

// ---------------------------------------------------------------------------
// Launch. Input order: hidden, time_decay, time_first, time_mix_key,
// time_mix_value, time_mix_receptance, Wk, Wv, Wr, Wo.
// ---------------------------------------------------------------------------
extern "C" void kernel_launch(void* const* d_in, const int* in_sizes, int n_in,
                              void* d_out, int out_size)
{
    const float* hidden = (const float*)d_in[0];
    const float* td     = (const float*)d_in[1];
    const float* tf     = (const float*)d_in[2];
    const float* mk     = (const float*)d_in[3];
    const float* mv     = (const float*)d_in[4];
    const float* mr     = (const float*)d_in[5];
    const float* Wk     = (const float*)d_in[6];
    const float* Wv     = (const float*)d_in[7];
    const float* Wr     = (const float*)d_in[8];
    const float* Wo     = (const float*)d_in[9];
    float* out          = (float*)d_out;

    // Host-side, idempotent, capture-safe (no stream work enqueued).
    cudaFuncSetAttribute(gemm_kvr, cudaFuncAttributeMaxDynamicSharedMemorySize, GEMM_SMEM);
    cudaFuncSetAttribute(gemm_o,   cudaFuncAttributeMaxDynamicSharedMemorySize, GEMM_SMEM);

    prep_w  <<<dim3(4096, 4), 256>>>(Wk, Wv, Wr, Wo);
    prep_act<<<16384, 256>>>(hidden, mk, mv, mr);

    gemm_kvr<<<dim3(HID / 128, MROWS / 128, 3), 128, GEMM_SMEM>>>();

    scan_pass1<<<(NCH * NSEG) / 256, 256>>>(td);
    scan_mid  <<<NCH / 256, 256>>>(td);
    scan_pass3<<<(NCH * NSEG) / 256, 256>>>(td, tf);

    gemm_o<<<dim3(HID / 128, MROWS / 128, 1), 128, GEMM_SMEM>>>(out);
}

// round 11
// speedup vs baseline: 4.6333x; 1.0677x over previous
#include <cuda_runtime.h>
#include <cuda_fp16.h>
#include <cstdint>
#include <math.h>

// Problem constants: B=4, S=2048, H=D=2048, fp32 I/O.
#define BATCH 4
#define SEQ   2048
#define HID   2048
#define MROWS (BATCH * SEQ)                 // 8192
#define MELEM ((size_t)MROWS * HID)         // 16,777,216
#define WELEM ((size_t)HID * HID)           // 4,194,304

// Segmented scan config
#define NSEG  32
#define SEG   (SEQ / NSEG)                  // 64
#define NCH   (BATCH * HID)                 // 8192

// ---------------------------------------------------------------------------
// Scratch (device globals; allocation is forbidden)
// ---------------------------------------------------------------------------
__device__ float g_K[MELEM];
__device__ float g_V[MELEM];
__device__ float g_R[MELEM];
__device__ __half g_Xhi[3 * MELEM];   // xk/xv/xr hi (fp16)
__device__ __half g_Xlo[3 * MELEM];   // xk/xv/xr lo (fp16)
__device__ __half g_Phi[MELEM];       // (r*wkv) hi
__device__ __half g_Plo[MELEM];       // (r*wkv) lo
__device__ __half g_Whi[4 * WELEM];   // Wk,Wv,Wr,Wo hi (fp16; no lo needed)
__device__ float g_sn[NCH * NSEG], g_sd[NCH * NSEG], g_sm[NCH * NSEG];
__device__ float g_pn[NCH * NSEG], g_pd[NCH * NSEG], g_pm[NCH * NSEG];

// ---------------------------------------------------------------------------
// Helpers
// ---------------------------------------------------------------------------
__device__ __forceinline__ uint32_t smem_to_u32(const void* p) {
    uint32_t a;
    asm("{ .reg .u64 t; cvta.to.shared.u64 t, %1; cvt.u32.u64 %0, t; }"
        : "=r"(a) : "l"(p));
    return a;
}
__device__ __forceinline__ void cp16(uint32_t dst, const void* src) {
    uint64_t g = (uint64_t)__cvta_generic_to_global((void*)src);
    asm volatile("cp.async.cg.shared.global [%0], [%1], 16;" :: "r"(dst), "l"(g));
}
__device__ __forceinline__ void ldsm_x4(uint32_t addr, uint32_t* r) {
    asm volatile("ldmatrix.sync.aligned.m8n8.x4.shared.b16 {%0,%1,%2,%3}, [%4];"
                 : "=r"(r[0]), "=r"(r[1]), "=r"(r[2]), "=r"(r[3]) : "r"(addr));
}
__device__ __forceinline__ void mma_f16(float* d, const uint32_t* a, const uint32_t* b) {
    asm volatile(
        "mma.sync.aligned.m16n8k16.row.col.f32.f16.f16.f32 "
        "{%0,%1,%2,%3}, {%4,%5,%6,%7}, {%8,%9}, {%0,%1,%2,%3};"
        : "+f"(d[0]), "+f"(d[1]), "+f"(d[2]), "+f"(d[3])
        : "r"(a[0]), "r"(a[1]), "r"(a[2]), "r"(a[3]), "r"(b[0]), "r"(b[1]));
}

// SMEM tile layout: 128 tile-rows x 32 fp16 (64B). Two tile-rows packed per
// 128B smem row; 16B chunk index XOR-swizzled by smem row for conflict-free
// cp.async stores AND ldmatrix reads.
__device__ __forceinline__ uint32_t swz(uint32_t row, uint32_t kc) {
    const uint32_t R = row >> 1;
    const uint32_t cidx = (((row & 1) << 2) | kc) ^ (R & 7);
    return R * 128 + cidx * 16;
}

// ---------------------------------------------------------------------------
// GEMM: C[m,n] = sum_k (Ahi[m,k]+Alo[m,k]) * B[n,k], single fused K-sweep.
// fp16 compensated split: dropped term A*B_lo ~ 2^-12 relative.
// CTA 128x128, BK=32, 8 warps (32x64 warp tiles), 3-stage cp.async pipeline,
// each stage holds {Ahi 8KB, Alo 8KB, B 8KB}; B fragments reused for hi+lo.
// 256 threads / __launch_bounds__(256,2) -> 16 warps/SM (4 per SMSP).
// ---------------------------------------------------------------------------
#define STAGE_BYTES 24576            // Ahi 8KB + Alo 8KB + B 8KB
#define GEMM_SMEM (3 * STAGE_BYTES)  // 72KB (dynamic, opt-in)
#define NIT 64                       // 2048 / 32

__device__ __forceinline__ void load_stage(uint32_t sbase, int cn,
                                           const __half* __restrict__ Ahi,
                                           const __half* __restrict__ Alo,
                                           const __half* __restrict__ Bp,
                                           int m0, int n0, int tid)
{
    const int kcol = cn * 32;
#pragma unroll
    for (int i = 0; i < 2; i++) {
        const int ch = tid + i * 256;          // 0..511
        const int row = ch >> 2, c = ch & 3;
        const uint32_t so = swz(row, c);
        const size_t goff = (size_t)(m0 + row) * HID + kcol + c * 8;
        cp16(sbase + so,         Ahi + goff);
        cp16(sbase + 8192 + so,  Alo + goff);
        cp16(sbase + 16384 + so, Bp + (size_t)(n0 + row) * HID + kcol + c * 8);
    }
    asm volatile("cp.async.commit_group;" ::: "memory");
}

__device__ void gemm_core(const __half* __restrict__ Ahi,
                          const __half* __restrict__ Alo,
                          const __half* __restrict__ Bhi,
                          float* __restrict__ C, bool sig)
{
    extern __shared__ char smem[];
    const uint32_t sb = smem_to_u32(smem);
    const int tid = threadIdx.x;
    const int lane = tid & 31;
    const int wid = tid >> 5;
    const int wm = (wid & 3) * 32;             // warp M offset (4 warps in M)
    const int wn = (wid >> 2) * 64;            // warp N offset (2 warps in N)
    const int m0 = blockIdx.y * 128, n0 = blockIdx.x * 128;

    float acc[2][8][4];
#pragma unroll
    for (int i = 0; i < 2; i++)
#pragma unroll
        for (int j = 0; j < 8; j++)
#pragma unroll
            for (int q = 0; q < 4; q++) acc[i][j][q] = 0.f;

    // Per-lane LDSM row/chunk components
    const int a_row = (lane & 15);
    const int a_kc  = (lane >> 4);
    const int b_row = ((lane >> 4) << 3) + (lane & 7);
    const int b_kc  = ((lane >> 3) & 1);

    // prologue: stages 0,1
    load_stage(sb,               0, Ahi, Alo, Bhi, m0, n0, tid);
    load_stage(sb + STAGE_BYTES, 1, Ahi, Alo, Bhi, m0, n0, tid);

    for (int it = 0; it < NIT; ++it) {
        if (it < NIT - 1) asm volatile("cp.async.wait_group 1;" ::: "memory");
        else              asm volatile("cp.async.wait_group 0;" ::: "memory");
        __syncthreads();

        const int cn = it + 2;
        if (cn < NIT)
            load_stage(sb + (cn % 3) * STAGE_BYTES, cn, Ahi, Alo, Bhi, m0, n0, tid);

        const uint32_t sA  = sb + (it % 3) * STAGE_BYTES;
        const uint32_t sAl = sA + 8192;
        const uint32_t sB  = sA + 16384;

#pragma unroll
        for (int kf = 0; kf < 2; kf++) {
            uint32_t ah[2][4], al[2][4], b[4][4];
#pragma unroll
            for (int mt = 0; mt < 2; mt++) {
                const uint32_t so = swz(wm + mt * 16 + a_row, kf * 2 + a_kc);
                ldsm_x4(sA + so,  ah[mt]);
                ldsm_x4(sAl + so, al[mt]);
            }
#pragma unroll
            for (int np = 0; np < 4; np++)
                ldsm_x4(sB + swz(wn + np * 16 + b_row, kf * 2 + b_kc), b[np]);
#pragma unroll
            for (int mt = 0; mt < 2; mt++)
#pragma unroll
                for (int nf = 0; nf < 8; nf++) {
                    mma_f16(acc[mt][nf], ah[mt], &b[nf >> 1][(nf & 1) * 2]);
                    mma_f16(acc[mt][nf], al[mt], &b[nf >> 1][(nf & 1) * 2]);
                }
        }
    }

    // epilogue: direct register -> GMEM
#pragma unroll
    for (int mt = 0; mt < 2; mt++) {
        const int r0 = m0 + wm + mt * 16 + (lane >> 2);
#pragma unroll
        for (int nf = 0; nf < 8; nf++) {
            const int col = n0 + wn + nf * 8 + 2 * (lane & 3);
            float2 v0 = make_float2(acc[mt][nf][0], acc[mt][nf][1]);
            float2 v1 = make_float2(acc[mt][nf][2], acc[mt][nf][3]);
            if (sig) {
                v0.x = 1.f / (1.f + __expf(-v0.x));
                v0.y = 1.f / (1.f + __expf(-v0.y));
                v1.x = 1.f / (1.f + __expf(-v1.x));
                v1.y = 1.f / (1.f + __expf(-v1.y));
            }
            *reinterpret_cast<float2*>(C + (size_t)r0 * HID + col)       = v0;
            *reinterpret_cast<float2*>(C + (size_t)(r0 + 8) * HID + col) = v1;
        }
    }
}

__global__ __launch_bounds__(256, 2)
void gemm_kvr()
{
    const int z = blockIdx.z;
    float* C = (z == 0) ? g_K : (z == 1) ? g_V : g_R;
    gemm_core(g_Xhi + (size_t)z * MELEM, g_Xlo + (size_t)z * MELEM,
              g_Whi + (size_t)z * WELEM, C, z == 2);
}

__global__ __launch_bounds__(256, 2)
void gemm_o(float* __restrict__ out)
{
    gemm_core(g_Phi, g_Plo, g_Whi + 3 * WELEM, out, false);
}

// ---------------------------------------------------------------------------
// Prep: fp16 hi/lo splits
// ---------------------------------------------------------------------------
__device__ __forceinline__ void split_store4(float a, float b, float c, float d,
                                             __half* ph, __half* pl)
{
    union { __half v[4]; uint2 u; } H, L;
    H.v[0] = __float2half_rn(a); L.v[0] = __float2half_rn(a - __half2float(H.v[0]));
    H.v[1] = __float2half_rn(b); L.v[1] = __float2half_rn(b - __half2float(H.v[1]));
    H.v[2] = __float2half_rn(c); L.v[2] = __float2half_rn(c - __half2float(H.v[2]));
    H.v[3] = __float2half_rn(d); L.v[3] = __float2half_rn(d - __half2float(H.v[3]));
    *reinterpret_cast<uint2*>(ph) = H.u;
    *reinterpret_cast<uint2*>(pl) = L.u;
}

__global__ __launch_bounds__(256)
void prep_w(const float* __restrict__ Wk, const float* __restrict__ Wv,
            const float* __restrict__ Wr, const float* __restrict__ Wo)
{
    const int y = blockIdx.y;
    const float* W = (y == 0) ? Wk : (y == 1) ? Wv : (y == 2) ? Wr : Wo;
    const size_t base = (size_t)y * WELEM;
    const size_t i4 = ((size_t)blockIdx.x * 256 + threadIdx.x) * 4;
    float4 w = *reinterpret_cast<const float4*>(W + i4);
    union { __half v[4]; uint2 u; } H;
    H.v[0] = __float2half_rn(w.x);
    H.v[1] = __float2half_rn(w.y);
    H.v[2] = __float2half_rn(w.z);
    H.v[3] = __float2half_rn(w.w);
    *reinterpret_cast<uint2*>(g_Whi + base + i4) = H.u;
}

__global__ __launch_bounds__(256)
void prep_act(const float* __restrict__ hidden, const float* __restrict__ mk,
              const float* __restrict__ mv, const float* __restrict__ mr)
{
    const size_t i4 = ((size_t)blockIdx.x * 256 + threadIdx.x) * 4;
    const int h = (int)(i4 & (HID - 1));
    const int s = (int)((i4 >> 11) & (SEQ - 1));
    const float4 cur = *reinterpret_cast<const float4*>(hidden + i4);
    float4 prv = make_float4(0.f, 0.f, 0.f, 0.f);
    if (s != 0) prv = *reinterpret_cast<const float4*>(hidden + i4 - HID);

    const float4 tk = *reinterpret_cast<const float4*>(mk + h);
    const float4 tv = *reinterpret_cast<const float4*>(mv + h);
    const float4 tr = *reinterpret_cast<const float4*>(mr + h);

    split_store4(fmaf(tk.x, cur.x - prv.x, prv.x), fmaf(tk.y, cur.y - prv.y, prv.y),
                 fmaf(tk.z, cur.z - prv.z, prv.z), fmaf(tk.w, cur.w - prv.w, prv.w),
                 g_Xhi + i4, g_Xlo + i4);
    split_store4(fmaf(tv.x, cur.x - prv.x, prv.x), fmaf(tv.y, cur.y - prv.y, prv.y),
                 fmaf(tv.z, cur.z - prv.z, prv.z), fmaf(tv.w, cur.w - prv.w, prv.w),
                 g_Xhi + MELEM + i4, g_Xlo + MELEM + i4);
    split_store4(fmaf(tr.x, cur.x - prv.x, prv.x), fmaf(tr.y, cur.y - prv.y, prv.y),
                 fmaf(tr.z, cur.z - prv.z, prv.z), fmaf(tr.w, cur.w - prv.w, prv.w),
                 g_Xhi + 2 * MELEM + i4, g_Xlo + 2 * MELEM + i4);
}

// ---------------------------------------------------------------------------
// WKV segmented scan (exp-stabilized linear recurrence -> associative)
// ---------------------------------------------------------------------------
__global__ void scan_pass1(const float* __restrict__ td)
{
    const int tid = blockIdx.x * blockDim.x + threadIdx.x;  // < NCH*NSEG
    const int d   = tid & (HID - 1);
    const int bs  = tid >> 11;
    const int seg = bs & (NSEG - 1);
    const int b   = bs >> 5;

    const float w = -__expf(td[d]);
    const size_t base = (size_t)(b * SEQ + seg * SEG) * HID + d;

    float num = 0.f, den = 0.f, mx = -1e38f;
#pragma unroll 4
    for (int i = 0; i < SEG; i++) {
        const size_t off = base + (size_t)i * HID;
        const float k = g_K[off];
        const float v = g_V[off];
        const float mn = fmaxf(mx + w, k);
        const float e1 = __expf(mx + w - mn);
        const float e2 = __expf(k - mn);
        num = e1 * num + e2 * v;
        den = e1 * den + e2;
        mx  = mn;
    }
    g_sn[tid] = num; g_sd[tid] = den; g_sm[tid] = mx;
}

__global__ void scan_mid(const float* __restrict__ td)
{
    const int tid = blockIdx.x * blockDim.x + threadIdx.x;  // < NCH
    const int d = tid & (HID - 1);
    const int b = tid >> 11;

    const float w = -__expf(td[d]);
    const float shift = w * (float)SEG;

    float N = 0.f, Dn = 0.f, M = -1e38f;
#pragma unroll
    for (int seg = 0; seg < NSEG; seg++) {
        const int idx = ((b * NSEG + seg) << 11) + d;
        g_pn[idx] = N; g_pd[idx] = Dn; g_pm[idx] = M;
        const float sn = g_sn[idx], sd = g_sd[idx], sm = g_sm[idx];
        const float mf = fmaxf(M + shift, sm);
        const float ea = __expf(M + shift - mf);
        const float eb = __expf(sm - mf);
        N  = ea * N  + eb * sn;
        Dn = ea * Dn + eb * sd;
        M  = mf;
    }
}

__global__ void scan_pass3(const float* __restrict__ td,
                           const float* __restrict__ tfv)
{
    const int tid = blockIdx.x * blockDim.x + threadIdx.x;  // < NCH*NSEG
    const int d   = tid & (HID - 1);
    const int bs  = tid >> 11;
    const int seg = bs & (NSEG - 1);
    const int b   = bs >> 5;

    const float w  = -__expf(td[d]);
    const float tf = tfv[d];
    float num = g_pn[tid], den = g_pd[tid], mx = g_pm[tid];

    const size_t base = (size_t)(b * SEQ + seg * SEG) * HID + d;
#pragma unroll 4
    for (int i = 0; i < SEG; i++) {
        const size_t off = base + (size_t)i * HID;
        const float k = g_K[off];
        const float v = g_V[off];

        const float mo  = fmaxf(mx, k + tf);
        const float o1  = __expf(mx - mo);
        const float o2  = __expf(k + tf - mo);
        const float out = (o1 * num + o2 * v) / (o1 * den + o2);

        const float mn = fmaxf(mx + w, k);
        const float e1 = __expf(mx + w - mn);
        const float e2 = __expf(k - mn);
        num = e1 * num + e2 * v;
        den = e1 * den + e2;
        mx  = mn;

        const float prod = g_R[off] * out;              // r * wkv
        const __half hi = __float2half_rn(prod);
        g_Phi[off] = hi;
        g_Plo[off] = __float2half_rn(prod - __half2float(hi));
    }
}

// ---------------------------------------------------------------------------
// Launch. Input order: hidden, time_decay, time_first, time_mix_key,
// time_mix_value, time_mix_receptance, Wk, Wv, Wr, Wo.
// ---------------------------------------------------------------------------
extern "C" void kernel_launch(void* const* d_in, const int* in_sizes, int n_in,
                              void* d_out, int out_size)
{
    const float* hidden = (const float*)d_in[0];
    const float* td     = (const float*)d_in[1];
    const float* tf     = (const float*)d_in[2];
    const float* mk     = (const float*)d_in[3];
    const float* mv     = (const float*)d_in[4];
    const float* mr     = (const float*)d_in[5];
    const float* Wk     = (const float*)d_in[6];
    const float* Wv     = (const float*)d_in[7];
    const float* Wr     = (const float*)d_in[8];
    const float* Wo     = (const float*)d_in[9];
    float* out          = (float*)d_out;

    // Host-side, idempotent, capture-safe (no stream work enqueued).
    cudaFuncSetAttribute(gemm_kvr, cudaFuncAttributeMaxDynamicSharedMemorySize, GEMM_SMEM);
    cudaFuncSetAttribute(gemm_o,   cudaFuncAttributeMaxDynamicSharedMemorySize, GEMM_SMEM);

    prep_w  <<<dim3(4096, 4), 256>>>(Wk, Wv, Wr, Wo);
    prep_act<<<16384, 256>>>(hidden, mk, mv, mr);

    gemm_kvr<<<dim3(HID / 128, MROWS / 128, 3), 256, GEMM_SMEM>>>();

    scan_pass1<<<(NCH * NSEG) / 256, 256>>>(td);
    scan_mid  <<<NCH / 256, 256>>>(td);
    scan_pass3<<<(NCH * NSEG) / 256, 256>>>(td, tf);

    gemm_o<<<dim3(HID / 128, MROWS / 128, 1), 256, GEMM_SMEM>>>(out);
}

// round 12
// speedup vs baseline: 6.0133x; 1.2979x over previous
#include <cuda_runtime.h>
#include <cuda_fp16.h>
#include <cstdint>
#include <math.h>

// Problem constants: B=4, S=2048, H=D=2048, fp32 I/O.
#define BATCH 4
#define SEQ   2048
#define HID   2048
#define MROWS (BATCH * SEQ)                 // 8192
#define MELEM ((size_t)MROWS * HID)         // 16,777,216
#define WELEM ((size_t)HID * HID)           // 4,194,304

// Segmented scan config
#define NSEG  32
#define SEG   (SEQ / NSEG)                  // 64
#define NCH   (BATCH * HID)                 // 8192

// ---------------------------------------------------------------------------
// Scratch (device globals; allocation is forbidden)
// ---------------------------------------------------------------------------
__device__ float g_K[MELEM];
__device__ float g_V[MELEM];
__device__ float g_R[MELEM];
__device__ __half g_X[3 * MELEM];     // xk/xv/xr (fp16)
__device__ __half g_P[MELEM];         // r*wkv (fp16)
__device__ __half g_W[4 * WELEM];     // Wk,Wv,Wr,Wo (fp16)
__device__ float g_sn[NCH * NSEG], g_sd[NCH * NSEG], g_sm[NCH * NSEG];
__device__ float g_pn[NCH * NSEG], g_pd[NCH * NSEG], g_pm[NCH * NSEG];

// ---------------------------------------------------------------------------
// Helpers
// ---------------------------------------------------------------------------
__device__ __forceinline__ uint32_t smem_to_u32(const void* p) {
    uint32_t a;
    asm("{ .reg .u64 t; cvta.to.shared.u64 t, %1; cvt.u32.u64 %0, t; }"
        : "=r"(a) : "l"(p));
    return a;
}
__device__ __forceinline__ void cp16(uint32_t dst, const void* src) {
    uint64_t g = (uint64_t)__cvta_generic_to_global((void*)src);
    asm volatile("cp.async.cg.shared.global [%0], [%1], 16;" :: "r"(dst), "l"(g));
}
__device__ __forceinline__ void ldsm_x4(uint32_t addr, uint32_t* r) {
    asm volatile("ldmatrix.sync.aligned.m8n8.x4.shared.b16 {%0,%1,%2,%3}, [%4];"
                 : "=r"(r[0]), "=r"(r[1]), "=r"(r[2]), "=r"(r[3]) : "r"(addr));
}
__device__ __forceinline__ void mma_f16(float* d, const uint32_t* a, const uint32_t* b) {
    asm volatile(
        "mma.sync.aligned.m16n8k16.row.col.f32.f16.f16.f32 "
        "{%0,%1,%2,%3}, {%4,%5,%6,%7}, {%8,%9}, {%0,%1,%2,%3};"
        : "+f"(d[0]), "+f"(d[1]), "+f"(d[2]), "+f"(d[3])
        : "r"(a[0]), "r"(a[1]), "r"(a[2]), "r"(a[3]), "r"(b[0]), "r"(b[1]));
}

// SMEM tile: 128 rows x 64 fp16 (128B rows). 16B chunk c (0..7) XOR-swizzled
// by (row & 7): conflict-free for cp.async stores and all ldmatrix phases.
__device__ __forceinline__ uint32_t swz64(uint32_t row, uint32_t c) {
    return row * 128 + ((c ^ (row & 7)) << 4);
}

// ---------------------------------------------------------------------------
// GEMM: C[m,n] = sum_k A[m,k] * B[n,k]; plain fp16 operands, fp32 accumulate
// (dropped terms A_lo*B + A*B_lo ~ 2^-12 relative each, incoherent).
// CTA 128x128, BK=64, 8 warps (32x64 warp tiles), 3-stage cp.async pipeline,
// stage = {A 16KB, B 16KB}. 256 threads, __launch_bounds__(256,2).
// ---------------------------------------------------------------------------
#define STAGE_BYTES 32768            // A 16KB + B 16KB
#define GEMM_SMEM (3 * STAGE_BYTES)  // 96KB (dynamic, opt-in)
#define NIT 32                       // 2048 / 64

__device__ __forceinline__ void load_stage(uint32_t sbase, int cn,
                                           const __half* __restrict__ Ap,
                                           const __half* __restrict__ Bp,
                                           int m0, int n0, int tid)
{
    const int kcol = cn * 64;
#pragma unroll
    for (int i = 0; i < 4; i++) {
        const int ch = tid + i * 256;          // 0..1023
        const int row = ch >> 3, c = ch & 7;
        const uint32_t so = swz64(row, c);
        cp16(sbase + so,         Ap + (size_t)(m0 + row) * HID + kcol + c * 8);
        cp16(sbase + 16384 + so, Bp + (size_t)(n0 + row) * HID + kcol + c * 8);
    }
    asm volatile("cp.async.commit_group;" ::: "memory");
}

__device__ void gemm_core(const __half* __restrict__ A,
                          const __half* __restrict__ B,
                          float* __restrict__ C, bool sig)
{
    extern __shared__ char smem[];
    const uint32_t sb = smem_to_u32(smem);
    const int tid = threadIdx.x;
    const int lane = tid & 31;
    const int wid = tid >> 5;
    const int wm = (wid & 3) * 32;             // warp M offset (4 warps in M)
    const int wn = (wid >> 2) * 64;            // warp N offset (2 warps in N)
    const int m0 = blockIdx.y * 128, n0 = blockIdx.x * 128;

    float acc[2][8][4];
#pragma unroll
    for (int i = 0; i < 2; i++)
#pragma unroll
        for (int j = 0; j < 8; j++)
#pragma unroll
            for (int q = 0; q < 4; q++) acc[i][j][q] = 0.f;

    // Per-lane LDSM row/chunk components
    const int a_row = (lane & 15);
    const int a_kc  = (lane >> 4);             // 16B half of 32B k-slice
    const int b_row = ((lane >> 4) << 3) + (lane & 7);
    const int b_kc  = ((lane >> 3) & 1);

    // prologue: stages 0,1
    load_stage(sb,               0, A, B, m0, n0, tid);
    load_stage(sb + STAGE_BYTES, 1, A, B, m0, n0, tid);

    for (int it = 0; it < NIT; ++it) {
        if (it < NIT - 1) asm volatile("cp.async.wait_group 1;" ::: "memory");
        else              asm volatile("cp.async.wait_group 0;" ::: "memory");
        __syncthreads();

        const int cn = it + 2;
        if (cn < NIT)
            load_stage(sb + (cn % 3) * STAGE_BYTES, cn, A, B, m0, n0, tid);

        const uint32_t sA = sb + (it % 3) * STAGE_BYTES;
        const uint32_t sB = sA + 16384;

#pragma unroll
        for (int kf = 0; kf < 4; kf++) {       // four k16 slices per BK=64
            uint32_t a[2][4], b[4][4];
#pragma unroll
            for (int mt = 0; mt < 2; mt++)
                ldsm_x4(sA + swz64(wm + mt * 16 + a_row, kf * 2 + a_kc), a[mt]);
#pragma unroll
            for (int np = 0; np < 4; np++)
                ldsm_x4(sB + swz64(wn + np * 16 + b_row, kf * 2 + b_kc), b[np]);
#pragma unroll
            for (int mt = 0; mt < 2; mt++)
#pragma unroll
                for (int nf = 0; nf < 8; nf++)
                    mma_f16(acc[mt][nf], a[mt], &b[nf >> 1][(nf & 1) * 2]);
        }
    }

    // epilogue: direct register -> GMEM
#pragma unroll
    for (int mt = 0; mt < 2; mt++) {
        const int r0 = m0 + wm + mt * 16 + (lane >> 2);
#pragma unroll
        for (int nf = 0; nf < 8; nf++) {
            const int col = n0 + wn + nf * 8 + 2 * (lane & 3);
            float2 v0 = make_float2(acc[mt][nf][0], acc[mt][nf][1]);
            float2 v1 = make_float2(acc[mt][nf][2], acc[mt][nf][3]);
            if (sig) {
                v0.x = 1.f / (1.f + __expf(-v0.x));
                v0.y = 1.f / (1.f + __expf(-v0.y));
                v1.x = 1.f / (1.f + __expf(-v1.x));
                v1.y = 1.f / (1.f + __expf(-v1.y));
            }
            *reinterpret_cast<float2*>(C + (size_t)r0 * HID + col)       = v0;
            *reinterpret_cast<float2*>(C + (size_t)(r0 + 8) * HID + col) = v1;
        }
    }
}

__global__ __launch_bounds__(256, 2)
void gemm_kvr()
{
    const int z = blockIdx.z;
    float* C = (z == 0) ? g_K : (z == 1) ? g_V : g_R;
    gemm_core(g_X + (size_t)z * MELEM, g_W + (size_t)z * WELEM, C, z == 2);
}

__global__ __launch_bounds__(256, 2)
void gemm_o(float* __restrict__ out)
{
    gemm_core(g_P, g_W + 3 * WELEM, out, false);
}

// ---------------------------------------------------------------------------
// Prep: fp16 conversions
// ---------------------------------------------------------------------------
__device__ __forceinline__ void h4_store(float a, float b, float c, float d, __half* p)
{
    union { __half v[4]; uint2 u; } H;
    H.v[0] = __float2half_rn(a);
    H.v[1] = __float2half_rn(b);
    H.v[2] = __float2half_rn(c);
    H.v[3] = __float2half_rn(d);
    *reinterpret_cast<uint2*>(p) = H.u;
}

__global__ __launch_bounds__(256)
void prep_w(const float* __restrict__ Wk, const float* __restrict__ Wv,
            const float* __restrict__ Wr, const float* __restrict__ Wo)
{
    const int y = blockIdx.y;
    const float* W = (y == 0) ? Wk : (y == 1) ? Wv : (y == 2) ? Wr : Wo;
    const size_t base = (size_t)y * WELEM;
    const size_t i4 = ((size_t)blockIdx.x * 256 + threadIdx.x) * 4;
    float4 w = *reinterpret_cast<const float4*>(W + i4);
    h4_store(w.x, w.y, w.z, w.w, g_W + base + i4);
}

__global__ __launch_bounds__(256)
void prep_act(const float* __restrict__ hidden, const float* __restrict__ mk,
              const float* __restrict__ mv, const float* __restrict__ mr)
{
    const size_t i4 = ((size_t)blockIdx.x * 256 + threadIdx.x) * 4;
    const int h = (int)(i4 & (HID - 1));
    const int s = (int)((i4 >> 11) & (SEQ - 1));
    const float4 cur = *reinterpret_cast<const float4*>(hidden + i4);
    float4 prv = make_float4(0.f, 0.f, 0.f, 0.f);
    if (s != 0) prv = *reinterpret_cast<const float4*>(hidden + i4 - HID);

    const float4 tk = *reinterpret_cast<const float4*>(mk + h);
    const float4 tv = *reinterpret_cast<const float4*>(mv + h);
    const float4 tr = *reinterpret_cast<const float4*>(mr + h);

    h4_store(fmaf(tk.x, cur.x - prv.x, prv.x), fmaf(tk.y, cur.y - prv.y, prv.y),
             fmaf(tk.z, cur.z - prv.z, prv.z), fmaf(tk.w, cur.w - prv.w, prv.w),
             g_X + i4);
    h4_store(fmaf(tv.x, cur.x - prv.x, prv.x), fmaf(tv.y, cur.y - prv.y, prv.y),
             fmaf(tv.z, cur.z - prv.z, prv.z), fmaf(tv.w, cur.w - prv.w, prv.w),
             g_X + MELEM + i4);
    h4_store(fmaf(tr.x, cur.x - prv.x, prv.x), fmaf(tr.y, cur.y - prv.y, prv.y),
             fmaf(tr.z, cur.z - prv.z, prv.z), fmaf(tr.w, cur.w - prv.w, prv.w),
             g_X + 2 * MELEM + i4);
}

// ---------------------------------------------------------------------------
// WKV segmented scan (exp-stabilized linear recurrence -> associative)
// ---------------------------------------------------------------------------
__global__ void scan_pass1(const float* __restrict__ td)
{
    const int tid = blockIdx.x * blockDim.x + threadIdx.x;  // < NCH*NSEG
    const int d   = tid & (HID - 1);
    const int bs  = tid >> 11;
    const int seg = bs & (NSEG - 1);
    const int b   = bs >> 5;

    const float w = -__expf(td[d]);
    const size_t base = (size_t)(b * SEQ + seg * SEG) * HID + d;

    float num = 0.f, den = 0.f, mx = -1e38f;
#pragma unroll 4
    for (int i = 0; i < SEG; i++) {
        const size_t off = base + (size_t)i * HID;
        const float k = g_K[off];
        const float v = g_V[off];
        const float mn = fmaxf(mx + w, k);
        const float e1 = __expf(mx + w - mn);
        const float e2 = __expf(k - mn);
        num = e1 * num + e2 * v;
        den = e1 * den + e2;
        mx  = mn;
    }
    g_sn[tid] = num; g_sd[tid] = den; g_sm[tid] = mx;
}

__global__ void scan_mid(const float* __restrict__ td)
{
    const int tid = blockIdx.x * blockDim.x + threadIdx.x;  // < NCH
    const int d = tid & (HID - 1);
    const int b = tid >> 11;

    const float w = -__expf(td[d]);
    const float shift = w * (float)SEG;

    float N = 0.f, Dn = 0.f, M = -1e38f;
#pragma unroll
    for (int seg = 0; seg < NSEG; seg++) {
        const int idx = ((b * NSEG + seg) << 11) + d;
        g_pn[idx] = N; g_pd[idx] = Dn; g_pm[idx] = M;
        const float sn = g_sn[idx], sd = g_sd[idx], sm = g_sm[idx];
        const float mf = fmaxf(M + shift, sm);
        const float ea = __expf(M + shift - mf);
        const float eb = __expf(sm - mf);
        N  = ea * N  + eb * sn;
        Dn = ea * Dn + eb * sd;
        M  = mf;
    }
}

__global__ void scan_pass3(const float* __restrict__ td,
                           const float* __restrict__ tfv)
{
    const int tid = blockIdx.x * blockDim.x + threadIdx.x;  // < NCH*NSEG
    const int d   = tid & (HID - 1);
    const int bs  = tid >> 11;
    const int seg = bs & (NSEG - 1);
    const int b   = bs >> 5;

    const float w  = -__expf(td[d]);
    const float tf = tfv[d];
    float num = g_pn[tid], den = g_pd[tid], mx = g_pm[tid];

    const size_t base = (size_t)(b * SEQ + seg * SEG) * HID + d;
#pragma unroll 4
    for (int i = 0; i < SEG; i++) {
        const size_t off = base + (size_t)i * HID;
        const float k = g_K[off];
        const float v = g_V[off];

        const float mo  = fmaxf(mx, k + tf);
        const float o1  = __expf(mx - mo);
        const float o2  = __expf(k + tf - mo);
        const float out = (o1 * num + o2 * v) / (o1 * den + o2);

        const float mn = fmaxf(mx + w, k);
        const float e1 = __expf(mx + w - mn);
        const float e2 = __expf(k - mn);
        num = e1 * num + e2 * v;
        den = e1 * den + e2;
        mx  = mn;

        g_P[off] = __float2half_rn(g_R[off] * out);     // r * wkv (fp16)
    }
}

// ---------------------------------------------------------------------------
// Launch. Input order: hidden, time_decay, time_first, time_mix_key,
// time_mix_value, time_mix_receptance, Wk, Wv, Wr, Wo.
// ---------------------------------------------------------------------------
extern "C" void kernel_launch(void* const* d_in, const int* in_sizes, int n_in,
                              void* d_out, int out_size)
{
    const float* hidden = (const float*)d_in[0];
    const float* td     = (const float*)d_in[1];
    const float* tf     = (const float*)d_in[2];
    const float* mk     = (const float*)d_in[3];
    const float* mv     = (const float*)d_in[4];
    const float* mr     = (const float*)d_in[5];
    const float* Wk     = (const float*)d_in[6];
    const float* Wv     = (const float*)d_in[7];
    const float* Wr     = (const float*)d_in[8];
    const float* Wo     = (const float*)d_in[9];
    float* out          = (float*)d_out;

    // Host-side, idempotent, capture-safe (no stream work enqueued).
    cudaFuncSetAttribute(gemm_kvr, cudaFuncAttributeMaxDynamicSharedMemorySize, GEMM_SMEM);
    cudaFuncSetAttribute(gemm_o,   cudaFuncAttributeMaxDynamicSharedMemorySize, GEMM_SMEM);

    prep_w  <<<dim3(4096, 4), 256>>>(Wk, Wv, Wr, Wo);
    prep_act<<<16384, 256>>>(hidden, mk, mv, mr);

    gemm_kvr<<<dim3(HID / 128, MROWS / 128, 3), 256, GEMM_SMEM>>>();

    scan_pass1<<<(NCH * NSEG) / 256, 256>>>(td);
    scan_mid  <<<NCH / 256, 256>>>(td);
    scan_pass3<<<(NCH * NSEG) / 256, 256>>>(td, tf);

    gemm_o<<<dim3(HID / 128, MROWS / 128, 1), 256, GEMM_SMEM>>>(out);
}

// round 13
// speedup vs baseline: 7.9085x; 1.3152x over previous
#include <cuda_runtime.h>
#include <cuda_fp16.h>
#include <cstdint>
#include <math.h>

// Problem constants: B=4, S=2048, H=D=2048, fp32 I/O.
#define BATCH 4
#define SEQ   2048
#define HID   2048
#define MROWS (BATCH * SEQ)                 // 8192
#define MELEM ((size_t)MROWS * HID)         // 16,777,216
#define WELEM ((size_t)HID * HID)           // 4,194,304

// Segmented scan config
#define NSEG  32
#define SEG   (SEQ / NSEG)                  // 64
#define NCH   (BATCH * HID)                 // 8192

// ---------------------------------------------------------------------------
// Scratch (device globals; allocation is forbidden)
// ---------------------------------------------------------------------------
__device__ float g_K[MELEM];
__device__ float g_V[MELEM];
__device__ __half g_Rh[MELEM];        // sigmoid(r) (fp16)
__device__ __half g_X[3 * MELEM];     // xk/xv/xr (fp16)
__device__ __half g_P[MELEM];         // r*wkv (fp16)
__device__ __half g_W[4 * WELEM];     // Wk,Wv,Wr,Wo (fp16)
__device__ float g_sn[NCH * NSEG], g_sd[NCH * NSEG], g_sm[NCH * NSEG];
__device__ float g_pn[NCH * NSEG], g_pd[NCH * NSEG], g_pm[NCH * NSEG];

// ---------------------------------------------------------------------------
// Helpers
// ---------------------------------------------------------------------------
__device__ __forceinline__ uint32_t smem_to_u32(const void* p) {
    uint32_t a;
    asm("{ .reg .u64 t; cvta.to.shared.u64 t, %1; cvt.u32.u64 %0, t; }"
        : "=r"(a) : "l"(p));
    return a;
}
__device__ __forceinline__ void cp16(uint32_t dst, const void* src) {
    uint64_t g = (uint64_t)__cvta_generic_to_global((void*)src);
    asm volatile("cp.async.cg.shared.global [%0], [%1], 16;" :: "r"(dst), "l"(g));
}
__device__ __forceinline__ void ldsm_x4(uint32_t addr, uint32_t* r) {
    asm volatile("ldmatrix.sync.aligned.m8n8.x4.shared.b16 {%0,%1,%2,%3}, [%4];"
                 : "=r"(r[0]), "=r"(r[1]), "=r"(r[2]), "=r"(r[3]) : "r"(addr));
}
__device__ __forceinline__ void mma_f16(float* d, const uint32_t* a, const uint32_t* b) {
    asm volatile(
        "mma.sync.aligned.m16n8k16.row.col.f32.f16.f16.f32 "
        "{%0,%1,%2,%3}, {%4,%5,%6,%7}, {%8,%9}, {%0,%1,%2,%3};"
        : "+f"(d[0]), "+f"(d[1]), "+f"(d[2]), "+f"(d[3])
        : "r"(a[0]), "r"(a[1]), "r"(a[2]), "r"(a[3]), "r"(b[0]), "r"(b[1]));
}

// SMEM tile: rows x 64 fp16 (128B rows). 16B chunk c (0..7) XOR-swizzled
// by (row & 7): conflict-free for cp.async stores and all ldmatrix phases.
__device__ __forceinline__ uint32_t swz64(uint32_t row, uint32_t c) {
    return row * 128 + ((c ^ (row & 7)) << 4);
}

// ---------------------------------------------------------------------------
// GEMM: C[m,n] = sum_k A[m,k] * B[n,k]; fp16 operands, fp32 accumulate.
// CTA 256x128, BK=64, 16 warps (64x32 warp tiles, 4Mx4N), 512 threads,
// 4-stage cp.async pipeline (48KB/stage, 192KB smem), 1 CTA/SM.
// mode: 0 = fp32 store, 1 = sigmoid -> fp16 store (g_Rh).
// ---------------------------------------------------------------------------
#define STAGE_BYTES 49152            // A 32KB + B 16KB
#define GEMM_SMEM (4 * STAGE_BYTES)  // 192KB (dynamic, opt-in)
#define NIT 32                       // 2048 / 64

__device__ __forceinline__ void load_stage(uint32_t sbase, int cn,
                                           const __half* __restrict__ Ap,
                                           const __half* __restrict__ Bp,
                                           int m0, int n0, int tid)
{
    const int kcol = cn * 64;
#pragma unroll
    for (int i = 0; i < 4; i++) {                    // A: 256 rows x 8 chunks
        const int ch = tid + i * 512;                // 0..2047
        const int row = ch >> 3, c = ch & 7;
        cp16(sbase + swz64(row, c), Ap + (size_t)(m0 + row) * HID + kcol + c * 8);
    }
#pragma unroll
    for (int i = 0; i < 2; i++) {                    // B: 128 rows x 8 chunks
        const int ch = tid + i * 512;                // 0..1023
        const int row = ch >> 3, c = ch & 7;
        cp16(sbase + 32768 + swz64(row, c), Bp + (size_t)(n0 + row) * HID + kcol + c * 8);
    }
    asm volatile("cp.async.commit_group;" ::: "memory");
}

__device__ void gemm_core(const __half* __restrict__ A,
                          const __half* __restrict__ B,
                          float* __restrict__ C, int mode)
{
    extern __shared__ char smem[];
    const uint32_t sb = smem_to_u32(smem);
    const int tid = threadIdx.x;
    const int lane = tid & 31;
    const int wid = tid >> 5;
    const int wm = (wid & 3) * 64;             // warp M offset (4 warps in M)
    const int wn = (wid >> 2) * 32;            // warp N offset (4 warps in N)
    const int m0 = blockIdx.y * 256, n0 = blockIdx.x * 128;

    float acc[4][4][4];
#pragma unroll
    for (int i = 0; i < 4; i++)
#pragma unroll
        for (int j = 0; j < 4; j++)
#pragma unroll
            for (int q = 0; q < 4; q++) acc[i][j][q] = 0.f;

    // Per-lane LDSM row/chunk components
    const int a_row = (lane & 15);
    const int a_kc  = (lane >> 4);             // 16B half of 32B k-slice
    const int b_row = ((lane >> 4) << 3) + (lane & 7);
    const int b_kc  = ((lane >> 3) & 1);

    // prologue: stages 0,1,2
    load_stage(sb,                   0, A, B, m0, n0, tid);
    load_stage(sb +     STAGE_BYTES, 1, A, B, m0, n0, tid);
    load_stage(sb + 2 * STAGE_BYTES, 2, A, B, m0, n0, tid);

    for (int it = 0; it < NIT; ++it) {
        if (it < NIT - 2)      asm volatile("cp.async.wait_group 2;" ::: "memory");
        else if (it == NIT - 2) asm volatile("cp.async.wait_group 1;" ::: "memory");
        else                   asm volatile("cp.async.wait_group 0;" ::: "memory");
        __syncthreads();

        const int cn = it + 3;
        if (cn < NIT)
            load_stage(sb + (cn & 3) * STAGE_BYTES, cn, A, B, m0, n0, tid);

        const uint32_t sA = sb + (it & 3) * STAGE_BYTES;
        const uint32_t sB = sA + 32768;

#pragma unroll
        for (int kf = 0; kf < 4; kf++) {       // four k16 slices per BK=64
            uint32_t a[4][4], b[2][4];
#pragma unroll
            for (int mt = 0; mt < 4; mt++)
                ldsm_x4(sA + swz64(wm + mt * 16 + a_row, kf * 2 + a_kc), a[mt]);
#pragma unroll
            for (int np = 0; np < 2; np++)
                ldsm_x4(sB + swz64(wn + np * 16 + b_row, kf * 2 + b_kc), b[np]);
#pragma unroll
            for (int mt = 0; mt < 4; mt++)
#pragma unroll
                for (int nf = 0; nf < 4; nf++)
                    mma_f16(acc[mt][nf], a[mt], &b[nf >> 1][(nf & 1) * 2]);
        }
    }

    // epilogue
#pragma unroll
    for (int mt = 0; mt < 4; mt++) {
        const int r0 = m0 + wm + mt * 16 + (lane >> 2);
#pragma unroll
        for (int nf = 0; nf < 4; nf++) {
            const int col = n0 + wn + nf * 8 + 2 * (lane & 3);
            if (mode == 1) {
                // sigmoid -> fp16 g_Rh
                float s0 = 1.f / (1.f + __expf(-acc[mt][nf][0]));
                float s1 = 1.f / (1.f + __expf(-acc[mt][nf][1]));
                float s2 = 1.f / (1.f + __expf(-acc[mt][nf][2]));
                float s3 = 1.f / (1.f + __expf(-acc[mt][nf][3]));
                *reinterpret_cast<__half2*>(g_Rh + (size_t)r0 * HID + col) =
                    __floats2half2_rn(s0, s1);
                *reinterpret_cast<__half2*>(g_Rh + (size_t)(r0 + 8) * HID + col) =
                    __floats2half2_rn(s2, s3);
            } else {
                *reinterpret_cast<float2*>(C + (size_t)r0 * HID + col) =
                    make_float2(acc[mt][nf][0], acc[mt][nf][1]);
                *reinterpret_cast<float2*>(C + (size_t)(r0 + 8) * HID + col) =
                    make_float2(acc[mt][nf][2], acc[mt][nf][3]);
            }
        }
    }
}

__global__ __launch_bounds__(512, 1)
void gemm_kvr()
{
    const int z = blockIdx.z;
    float* C = (z == 0) ? g_K : (z == 1) ? g_V : nullptr;
    gemm_core(g_X + (size_t)z * MELEM, g_W + (size_t)z * WELEM, C, z == 2 ? 1 : 0);
}

__global__ __launch_bounds__(512, 1)
void gemm_o(float* __restrict__ out)
{
    gemm_core(g_P, g_W + 3 * WELEM, out, 0);
}

// ---------------------------------------------------------------------------
// Prep: fp16 conversions
// ---------------------------------------------------------------------------
__device__ __forceinline__ void h4_store(float a, float b, float c, float d, __half* p)
{
    union { __half v[4]; uint2 u; } H;
    H.v[0] = __float2half_rn(a);
    H.v[1] = __float2half_rn(b);
    H.v[2] = __float2half_rn(c);
    H.v[3] = __float2half_rn(d);
    *reinterpret_cast<uint2*>(p) = H.u;
}

__global__ __launch_bounds__(256)
void prep_w(const float* __restrict__ Wk, const float* __restrict__ Wv,
            const float* __restrict__ Wr, const float* __restrict__ Wo)
{
    const int y = blockIdx.y;
    const float* W = (y == 0) ? Wk : (y == 1) ? Wv : (y == 2) ? Wr : Wo;
    const size_t base = (size_t)y * WELEM;
    const size_t i4 = ((size_t)blockIdx.x * 256 + threadIdx.x) * 4;
    float4 w = *reinterpret_cast<const float4*>(W + i4);
    h4_store(w.x, w.y, w.z, w.w, g_W + base + i4);
}

__global__ __launch_bounds__(256)
void prep_act(const float* __restrict__ hidden, const float* __restrict__ mk,
              const float* __restrict__ mv, const float* __restrict__ mr)
{
    const size_t i4 = ((size_t)blockIdx.x * 256 + threadIdx.x) * 4;
    const int h = (int)(i4 & (HID - 1));
    const int s = (int)((i4 >> 11) & (SEQ - 1));
    const float4 cur = *reinterpret_cast<const float4*>(hidden + i4);
    float4 prv = make_float4(0.f, 0.f, 0.f, 0.f);
    if (s != 0) prv = *reinterpret_cast<const float4*>(hidden + i4 - HID);

    const float4 tk = *reinterpret_cast<const float4*>(mk + h);
    const float4 tv = *reinterpret_cast<const float4*>(mv + h);
    const float4 tr = *reinterpret_cast<const float4*>(mr + h);

    h4_store(fmaf(tk.x, cur.x - prv.x, prv.x), fmaf(tk.y, cur.y - prv.y, prv.y),
             fmaf(tk.z, cur.z - prv.z, prv.z), fmaf(tk.w, cur.w - prv.w, prv.w),
             g_X + i4);
    h4_store(fmaf(tv.x, cur.x - prv.x, prv.x), fmaf(tv.y, cur.y - prv.y, prv.y),
             fmaf(tv.z, cur.z - prv.z, prv.z), fmaf(tv.w, cur.w - prv.w, prv.w),
             g_X + MELEM + i4);
    h4_store(fmaf(tr.x, cur.x - prv.x, prv.x), fmaf(tr.y, cur.y - prv.y, prv.y),
             fmaf(tr.z, cur.z - prv.z, prv.z), fmaf(tr.w, cur.w - prv.w, prv.w),
             g_X + 2 * MELEM + i4);
}

// ---------------------------------------------------------------------------
// WKV segmented scan (exp-stabilized linear recurrence -> associative)
// ---------------------------------------------------------------------------
__global__ void scan_pass1(const float* __restrict__ td)
{
    const int tid = blockIdx.x * blockDim.x + threadIdx.x;  // < NCH*NSEG
    const int d   = tid & (HID - 1);
    const int bs  = tid >> 11;
    const int seg = bs & (NSEG - 1);
    const int b   = bs >> 5;

    const float w = -__expf(td[d]);
    const size_t base = (size_t)(b * SEQ + seg * SEG) * HID + d;

    float num = 0.f, den = 0.f, mx = -1e38f;
#pragma unroll 4
    for (int i = 0; i < SEG; i++) {
        const size_t off = base + (size_t)i * HID;
        const float k = g_K[off];
        const float v = g_V[off];
        const float mn = fmaxf(mx + w, k);
        const float e1 = __expf(mx + w - mn);
        const float e2 = __expf(k - mn);
        num = e1 * num + e2 * v;
        den = e1 * den + e2;
        mx  = mn;
    }
    g_sn[tid] = num; g_sd[tid] = den; g_sm[tid] = mx;
}

__global__ void scan_mid(const float* __restrict__ td)
{
    const int tid = blockIdx.x * blockDim.x + threadIdx.x;  // < NCH
    const int d = tid & (HID - 1);
    const int b = tid >> 11;

    const float w = -__expf(td[d]);
    const float shift = w * (float)SEG;

    float N = 0.f, Dn = 0.f, M = -1e38f;
#pragma unroll
    for (int seg = 0; seg < NSEG; seg++) {
        const int idx = ((b * NSEG + seg) << 11) + d;
        g_pn[idx] = N; g_pd[idx] = Dn; g_pm[idx] = M;
        const float sn = g_sn[idx], sd = g_sd[idx], sm = g_sm[idx];
        const float mf = fmaxf(M + shift, sm);
        const float ea = __expf(M + shift - mf);
        const float eb = __expf(sm - mf);
        N  = ea * N  + eb * sn;
        Dn = ea * Dn + eb * sd;
        M  = mf;
    }
}

__global__ void scan_pass3(const float* __restrict__ td,
                           const float* __restrict__ tfv)
{
    const int tid = blockIdx.x * blockDim.x + threadIdx.x;  // < NCH*NSEG
    const int d   = tid & (HID - 1);
    const int bs  = tid >> 11;
    const int seg = bs & (NSEG - 1);
    const int b   = bs >> 5;

    const float w  = -__expf(td[d]);
    const float tf = tfv[d];
    float num = g_pn[tid], den = g_pd[tid], mx = g_pm[tid];

    const size_t base = (size_t)(b * SEQ + seg * SEG) * HID + d;
#pragma unroll 4
    for (int i = 0; i < SEG; i++) {
        const size_t off = base + (size_t)i * HID;
        const float k = g_K[off];
        const float v = g_V[off];

        const float mo  = fmaxf(mx, k + tf);
        const float o1  = __expf(mx - mo);
        const float o2  = __expf(k + tf - mo);
        const float out = (o1 * num + o2 * v) / (o1 * den + o2);

        const float mn = fmaxf(mx + w, k);
        const float e1 = __expf(mx + w - mn);
        const float e2 = __expf(k - mn);
        num = e1 * num + e2 * v;
        den = e1 * den + e2;
        mx  = mn;

        g_P[off] = __float2half_rn(__half2float(g_Rh[off]) * out);  // r * wkv
    }
}

// ---------------------------------------------------------------------------
// Launch. Input order: hidden, time_decay, time_first, time_mix_key,
// time_mix_value, time_mix_receptance, Wk, Wv, Wr, Wo.
// ---------------------------------------------------------------------------
extern "C" void kernel_launch(void* const* d_in, const int* in_sizes, int n_in,
                              void* d_out, int out_size)
{
    const float* hidden = (const float*)d_in[0];
    const float* td     = (const float*)d_in[1];
    const float* tf     = (const float*)d_in[2];
    const float* mk     = (const float*)d_in[3];
    const float* mv     = (const float*)d_in[4];
    const float* mr     = (const float*)d_in[5];
    const float* Wk     = (const float*)d_in[6];
    const float* Wv     = (const float*)d_in[7];
    const float* Wr     = (const float*)d_in[8];
    const float* Wo     = (const float*)d_in[9];
    float* out          = (float*)d_out;

    // Host-side, idempotent, capture-safe (no stream work enqueued).
    cudaFuncSetAttribute(gemm_kvr, cudaFuncAttributeMaxDynamicSharedMemorySize, GEMM_SMEM);
    cudaFuncSetAttribute(gemm_o,   cudaFuncAttributeMaxDynamicSharedMemorySize, GEMM_SMEM);

    prep_w  <<<dim3(4096, 4), 256>>>(Wk, Wv, Wr, Wo);
    prep_act<<<16384, 256>>>(hidden, mk, mv, mr);

    gemm_kvr<<<dim3(HID / 128, MROWS / 256, 3), 512, GEMM_SMEM>>>();

    scan_pass1<<<(NCH * NSEG) / 256, 256>>>(td);
    scan_mid  <<<NCH / 256, 256>>>(td);
    scan_pass3<<<(NCH * NSEG) / 256, 256>>>(td, tf);

    gemm_o<<<dim3(HID / 128, MROWS / 256, 1), 512, GEMM_SMEM>>>(out);
}